// round 12
// baseline (speedup 1.0000x reference)
#include <cuda_runtime.h>
#include <cuda_fp16.h>
#include <cstdint>

// Problem constants
#define S_LEN  1024
#define HID    1024
#define NH     16
#define DK     64
#define BATCH  4
#define M_TOT  (BATCH * S_LEN)     // 4096
#define QK_SCALE 0.125f            // 64^-0.5
#define NEGV   (-9e15f)

// Scratch (static device globals — allocation-free per harness rules)
__device__ __align__(256) __half g_q16 [BATCH * NH * S_LEN * DK];  // [b][h][s][d], pre-scaled
__device__ __align__(256) __half g_k16 [BATCH * NH * S_LEN * DK];  // [b][h][s][d]
__device__ __align__(256) __half g_vt16[BATCH * NH * DK * S_LEN];  // [b][h][d][s]  (V^T)
__device__ __align__(256) __half g_att16[M_TOT * HID];             // attn out
__device__ __align__(256) __half g_x16 [M_TOT * HID];              // fp16 batch
__device__ __align__(256) __half g_wq16[HID * HID];
__device__ __align__(256) __half g_wk16[HID * HID];
__device__ __align__(256) __half g_wv16[HID * HID];
__device__ __align__(256) __half g_wo16[HID * HID];

__device__ __forceinline__ uint32_t smem_u32(const void* p) {
    uint32_t a;
    asm("{ .reg .u64 t; cvta.to.shared.u64 t, %1; cvt.u32.u64 %0, t; }"
        : "=r"(a) : "l"(p));
    return a;
}
__device__ __forceinline__ void cpasync16(uint32_t dst, const void* src) {
    asm volatile("cp.async.ca.shared.global [%0], [%1], 16;"
                 :: "r"(dst), "l"(src) : "memory");
}
__device__ __forceinline__ void cpasync_commit() {
    asm volatile("cp.async.commit_group;" ::: "memory");
}
__device__ __forceinline__ void cpasync_wait0() {
    asm volatile("cp.async.wait_group 0;" ::: "memory");
}
__device__ __forceinline__ void cpasync_wait1() {
    asm volatile("cp.async.wait_group 1;" ::: "memory");
}

// fp16 MMA, fp32 accumulate: D(16x8) += A(16x16) * B(16x8)
__device__ __forceinline__ void mma_f16(float c[4], const uint32_t a[4],
                                        const uint32_t b[2]) {
    asm volatile(
        "mma.sync.aligned.m16n8k16.row.col.f32.f16.f16.f32 "
        "{%0,%1,%2,%3}, {%4,%5,%6,%7}, {%8,%9}, {%0,%1,%2,%3};"
        : "+f"(c[0]), "+f"(c[1]), "+f"(c[2]), "+f"(c[3])
        : "r"(a[0]), "r"(a[1]), "r"(a[2]), "r"(a[3]),
          "r"(b[0]), "r"(b[1]));
}

// Fast exp on the FMA pipe. Rel err ~4e-5.
__device__ __forceinline__ float fexp(float x) {
    float z = x * 1.44269504f;
    z = fmaxf(z, -125.0f);
    const float C = 12582912.0f;            // 1.5 * 2^23
    float nf = z + C;
    int n = __float_as_int(nf) - 0x4B400000;
    float f = z - (nf - C);
    float p = 0.00961813f;
    p = fmaf(p, f, 0.0555041f);
    p = fmaf(p, f, 0.240227f);
    p = fmaf(p, f, 0.693147f);
    p = fmaf(p, f, 1.0f);
    return __int_as_float(__float_as_int(p) + (n << 23));
}

// ---------------------------------------------------------------------------
// Pre-round pass: batch + 4 weights -> fp16 scratch (single launch).
// ---------------------------------------------------------------------------
#define G8X (M_TOT * HID / 8)   // 524288
#define G8W (HID * HID / 8)     // 131072 = 2^17

__global__ __launch_bounds__(256) void round_all16(
    const float4* __restrict__ x,
    const float4* __restrict__ wq, const float4* __restrict__ wk,
    const float4* __restrict__ wv, const float4* __restrict__ wo,
    __half* __restrict__ ox,
    __half* __restrict__ owq, __half* __restrict__ owk,
    __half* __restrict__ owv, __half* __restrict__ owo)
{
    const int i = blockIdx.x * 256 + threadIdx.x;
    const float4* src;
    __half* dst;
    int off;
    if (i < G8X) {
        src = x; dst = ox; off = i;
    } else {
        const int j = i - G8X;
        const int sel = j >> 17;
        off = j & (G8W - 1);
        src = sel == 0 ? wq : (sel == 1 ? wk : (sel == 2 ? wv : wo));
        dst = sel == 0 ? owq : (sel == 1 ? owk : (sel == 2 ? owv : owo));
    }
    float4 v0 = src[off * 2];
    float4 v1 = src[off * 2 + 1];
    __half2 h[4];
    h[0] = __float22half2_rn(make_float2(v0.x, v0.y));
    h[1] = __float22half2_rn(make_float2(v0.z, v0.w));
    h[2] = __float22half2_rn(make_float2(v1.x, v1.y));
    h[3] = __float22half2_rn(make_float2(v1.z, v1.w));
    *(uint4*)(dst + (size_t)off * 8) = *(const uint4*)h;
}

// ---------------------------------------------------------------------------
// GEMM core: FP16 mma.sync (m16n8k16, fp32 accum), 128x128 tile, BK=32,
// 8 warps, 3-stage cp.async pipeline. Rows: 32 fp16, pitch 80 B.
// ---------------------------------------------------------------------------
#define PITCHB  80
#define TILEB   (128 * PITCHB)          // 10240 B per operand tile
#define STAGEB  (2 * TILEB)             // 20480
#define GEMM_SMEM_BYTES (3 * STAGEB)    // 61440

#define LOAD_STAGE(s, kk)                                                     \
    do {                                                                      \
        const uint32_t base = sbase + (uint32_t)(s) * STAGEB;                 \
        _Pragma("unroll")                                                     \
        for (int t = 0; t < 2; ++t) {                                         \
            const int idx = tid + t * 256;                                    \
            const int row = idx >> 2, c4 = idx & 3;                           \
            cpasync16(base + row * PITCHB + c4 * 16,                          \
                      Ap + (size_t)(bm + row) * 1024 + (kk) + c4 * 8);        \
            cpasync16(base + TILEB + row * PITCHB + c4 * 16,                  \
                      Wp + (size_t)(bn + row) * 1024 + (kk) + c4 * 8);        \
        }                                                                     \
        cpasync_commit();                                                     \
    } while (0)

#define GEMM_MAINLOOP16()                                                     \
    LOAD_STAGE(0, 0);                                                         \
    LOAD_STAGE(1, 32);                                                        \
    for (int i = 0; i < 32; ++i) {                                            \
        if (i >= 30) cpasync_wait0(); else cpasync_wait1();                   \
        __syncthreads();                                                      \
        if (i + 2 < 32) {                                                     \
            const int s2 = (i + 2) % 3;                                       \
            LOAD_STAGE(s2, (i + 2) * 32);                                     \
        }                                                                     \
        const char* Sb = (const char*)sm + (i % 3) * STAGEB;                  \
        _Pragma("unroll")                                                     \
        for (int ks = 0; ks < 2; ++ks) {                                      \
            const int kbB = ks * 32;                                          \
            uint32_t af[2][4];                                                \
            _Pragma("unroll")                                                 \
            for (int mi = 0; mi < 2; ++mi) {                                  \
                const char* p = Sb + (wm * 32 + mi * 16 + g) * PITCHB         \
                                + kbB + tg * 4;                               \
                af[mi][0] = *(const uint32_t*)(p);                            \
                af[mi][1] = *(const uint32_t*)(p + 8 * PITCHB);               \
                af[mi][2] = *(const uint32_t*)(p + 16);                       \
                af[mi][3] = *(const uint32_t*)(p + 8 * PITCHB + 16);          \
            }                                                                 \
            uint32_t bf[8][2];                                                \
            _Pragma("unroll")                                                 \
            for (int ni = 0; ni < 8; ++ni) {                                  \
                const char* p = Sb + TILEB + (wn * 64 + ni * 8 + g) * PITCHB  \
                                + kbB + tg * 4;                               \
                bf[ni][0] = *(const uint32_t*)(p);                            \
                bf[ni][1] = *(const uint32_t*)(p + 16);                       \
            }                                                                 \
            _Pragma("unroll")                                                 \
            for (int mi = 0; mi < 2; ++mi)                                    \
                _Pragma("unroll")                                             \
                for (int ni = 0; ni < 8; ++ni)                                \
                    mma_f16(c[mi][ni], af[mi], bf[ni]);                       \
        }                                                                     \
    }

// Fused QKV projection: grid (24, 32); bx>>3 selects {Q,K,V}.
__global__ __launch_bounds__(256, 2) void gemm_qkv(
    const __half* __restrict__ A,
    const __half* __restrict__ Wqp, const __half* __restrict__ Wkp,
    const __half* __restrict__ Wvp,
    const float* __restrict__ bq, const float* __restrict__ bk,
    const float* __restrict__ bv,
    __half* __restrict__ oq, __half* __restrict__ ok, __half* __restrict__ ovt)
{
    extern __shared__ float sm[];
    const uint32_t sbase = smem_u32(sm);

    const int tid = threadIdx.x;
    const int wid = tid >> 5, lid = tid & 31;
    const int which = blockIdx.x >> 3;
    const int bn = (blockIdx.x & 7) * 128;
    const int bm = blockIdx.y * 128;
    const int wm = wid >> 1, wn = wid & 1;
    const int g = lid >> 2, tg = lid & 3;

    const __half* Wp  = which == 0 ? Wqp : (which == 1 ? Wkp : Wvp);
    const float* bias = which == 0 ? bq  : (which == 1 ? bk  : bv);
    const __half* Ap = A;

    float c[2][8][4];
#pragma unroll
    for (int mi = 0; mi < 2; ++mi)
#pragma unroll
        for (int ni = 0; ni < 8; ++ni)
#pragma unroll
            for (int k = 0; k < 4; ++k) c[mi][ni][k] = 0.0f;

    GEMM_MAINLOOP16();

    if (which < 2) {
        __half* out = which == 0 ? oq : ok;
        const float scale = which == 0 ? QK_SCALE : 1.0f;
#pragma unroll
        for (int mi = 0; mi < 2; ++mi) {
            const int rowa = bm + wm * 32 + mi * 16 + g;
            const int rowb = rowa + 8;
#pragma unroll
            for (int ni = 0; ni < 8; ++ni) {
                const int col = bn + wn * 64 + ni * 8 + tg * 2;
                const float b0 = bias[col], b1 = bias[col + 1];
                __half2 h0 = __float22half2_rn(
                    make_float2((c[mi][ni][0] + b0) * scale,
                                (c[mi][ni][1] + b1) * scale));
                __half2 h1 = __float22half2_rn(
                    make_float2((c[mi][ni][2] + b0) * scale,
                                (c[mi][ni][3] + b1) * scale));
                const int h = col >> 6, d = col & 63;
                const int ba = rowa >> 10, sa = rowa & 1023;
                const int bb = rowb >> 10, sb2 = rowb & 1023;
                *(__half2*)(out + (((size_t)(ba * NH + h) * S_LEN + sa) * DK + d)) = h0;
                *(__half2*)(out + (((size_t)(bb * NH + h) * S_LEN + sb2) * DK + d)) = h1;
            }
        }
    } else {
        // V: stage transposed [n][m] fp16 tile (pitch 136 halfs)
        __syncthreads();
        __half* st = (__half*)sm;
#pragma unroll
        for (int mi = 0; mi < 2; ++mi) {
            const int ma = wm * 32 + mi * 16 + g;
            const int mb = ma + 8;
#pragma unroll
            for (int ni = 0; ni < 8; ++ni) {
                const int nl = wn * 64 + ni * 8 + tg * 2;
                const float b0 = bias[bn + nl], b1 = bias[bn + nl + 1];
                st[(nl + 0) * 136 + ma] = __float2half_rn(c[mi][ni][0] + b0);
                st[(nl + 1) * 136 + ma] = __float2half_rn(c[mi][ni][1] + b1);
                st[(nl + 0) * 136 + mb] = __float2half_rn(c[mi][ni][2] + b0);
                st[(nl + 1) * 136 + mb] = __float2half_rn(c[mi][ni][3] + b1);
            }
        }
        __syncthreads();
        const int r = tid >> 1, sel = tid & 1;
        const int col = bn + r;
        const int hh = col >> 6, d = col & 63;
        const int bb2 = bm >> 10;
        const int s0 = (bm & 1023) + sel * 64;
        __half* dst = ovt + (((size_t)(bb2 * NH + hh) * DK + d) * S_LEN + s0);
        const __half* srcp = st + r * 136 + sel * 64;
#pragma unroll
        for (int k2 = 0; k2 < 8; ++k2)
            *(uint4*)(dst + k2 * 8) = *(const uint4*)(srcp + k2 * 8);
    }
}

// Output projection: fp16 inputs, row-major fp32 out.
__global__ __launch_bounds__(256, 2) void gemm_o(
    const __half* __restrict__ A, const __half* __restrict__ W,
    const float* __restrict__ bias, float* __restrict__ out)
{
    extern __shared__ float sm[];
    const uint32_t sbase = smem_u32(sm);

    const int tid = threadIdx.x;
    const int wid = tid >> 5, lid = tid & 31;
    const int bn = blockIdx.x * 128;
    const int bm = blockIdx.y * 128;
    const int wm = wid >> 1, wn = wid & 1;
    const int g = lid >> 2, tg = lid & 3;
    const __half* Ap = A;
    const __half* Wp = W;

    float c[2][8][4];
#pragma unroll
    for (int mi = 0; mi < 2; ++mi)
#pragma unroll
        for (int ni = 0; ni < 8; ++ni)
#pragma unroll
            for (int k = 0; k < 4; ++k) c[mi][ni][k] = 0.0f;

    GEMM_MAINLOOP16();

#pragma unroll
    for (int mi = 0; mi < 2; ++mi) {
        const int rowa = bm + wm * 32 + mi * 16 + g;
        const int rowb = rowa + 8;
#pragma unroll
        for (int ni = 0; ni < 8; ++ni) {
            const int col = bn + wn * 64 + ni * 8 + tg * 2;
            const float b0 = bias[col], b1 = bias[col + 1];
            *(float2*)(out + (size_t)rowa * HID + col) =
                make_float2(c[mi][ni][0] + b0, c[mi][ni][1] + b1);
            *(float2*)(out + (size_t)rowb * HID + col) =
                make_float2(c[mi][ni][2] + b0, c[mi][ni][3] + b1);
        }
    }
}

// ---------------------------------------------------------------------------
// FP16 tensor-core flash attention. K-tiles of 32. Fixed-zero-max softmax.
// Q fragments hoisted to registers (loaded once). Bias via direct batched
// LDG (no smem staging). cp.async double-buffered K and V^T only.
// CTA: 128 q, 8 warps x 16 q-rows.
// Smem bytes: Q[128x144] | K0,K1[32x144] | Vt0,Vt1[64x80] = 37888
// ---------------------------------------------------------------------------
#define QPITCH 144
#define VPITCH 80
#define QS_B   0
#define K0_B   (128 * QPITCH)                      // 18432
#define K1_B   (K0_B + 32 * QPITCH)                // 23040
#define V0_B   (K1_B + 32 * QPITCH)                // 27648
#define V1_B   (V0_B + 64 * VPITCH)                // 32768
#define ATTN_SMEM_BYTES (V1_B + 64 * VPITCH)       // 37888

#define KT_N   32
#define NTILES (S_LEN / KT_N)                      // 32

__global__ __launch_bounds__(256, 2) void attn_mma(
    const __half* __restrict__ Qg, const __half* __restrict__ Kg,
    const __half* __restrict__ Vt, const float* __restrict__ Bias,
    __half* __restrict__ O)
{
    extern __shared__ float sm[];
    char* smc = (char*)sm;
    const uint32_t sb = smem_u32(sm);
    const uint32_t KbB[2] = { sb + K0_B, sb + K1_B };
    const uint32_t VbB[2] = { sb + V0_B, sb + V1_B };
    const char* Kc[2] = { smc + K0_B, smc + K1_B };
    const char* Vc[2] = { smc + V0_B, smc + V1_B };

    const int q0 = blockIdx.x * 128;
    const int h  = blockIdx.y;
    const int b  = blockIdx.z;
    const int bh = b * NH + h;

    const __half* qp = Qg + (size_t)bh * S_LEN * DK + (size_t)q0 * DK;
    const __half* kp = Kg + (size_t)bh * S_LEN * DK;
    const __half* vtp = Vt + (size_t)bh * DK * S_LEN;
    const float* bp = Bias + (size_t)bh * S_LEN * S_LEN + (size_t)q0 * S_LEN;

    const int tid = threadIdx.x;
    const int wid = tid >> 5, lid = tid & 31;
    const int g = lid >> 2, tg = lid & 3;
    const int qb = wid * 16;
    const int qrow0 = q0 + qb + g;

    // Per-tile async loads: K 32x64 fp16 (256 chunks), Vt 64x32 fp16 (256).
#define LOAD_TILE(st, kt)                                                     \
    do {                                                                      \
        {                                                                     \
            const int row = tid >> 3, off = tid & 7;                          \
            cpasync16(KbB[st] + row * QPITCH + off * 16,                      \
                      kp + (size_t)((kt) * KT_N + row) * 64 + off * 8);       \
        }                                                                     \
        {                                                                     \
            const int row = tid >> 2, off = tid & 3;                          \
            cpasync16(VbB[st] + row * VPITCH + off * 16,                      \
                      vtp + (size_t)row * S_LEN + (kt) * KT_N + off * 8);     \
        }                                                                     \
        cpasync_commit();                                                     \
    } while (0)

    // Prologue: Q tile (1024 chunks) + K/V tile 0 (single group)
#pragma unroll
    for (int i = 0; i < 4; ++i) {
        const int cidx = tid + i * 256;
        const int row = cidx >> 3, off = cidx & 7;
        cpasync16(sb + QS_B + row * QPITCH + off * 16, qp + row * 64 + off * 8);
    }
    LOAD_TILE(0, 0);
    cpasync_wait0();
    __syncthreads();

    // Hoist Q fragments into registers (tile-invariant).
    uint32_t qf[4][4];
#pragma unroll
    for (int kcb = 0; kcb < 4; ++kcb) {
        const char* qa = smc + QS_B + (qb + g) * QPITCH + (kcb * 16 + 2 * tg) * 2;
        qf[kcb][0] = *(const uint32_t*)(qa);
        qf[kcb][1] = *(const uint32_t*)(qa + 8 * QPITCH);
        qf[kcb][2] = *(const uint32_t*)(qa + 16);
        qf[kcb][3] = *(const uint32_t*)(qa + 8 * QPITCH + 16);
    }

    float l0 = 0.0f, l1 = 0.0f;
    float acc[8][4];
#pragma unroll
    for (int ni = 0; ni < 8; ++ni)
#pragma unroll
        for (int j = 0; j < 4; ++j) acc[ni][j] = 0.0f;

    for (int kt = 0; kt < NTILES; ++kt) {
        const int cur = kt & 1;
        if (kt + 1 < NTILES) LOAD_TILE(cur ^ 1, kt + 1);

        // Batched bias loads (issued before QK MMAs for latency overlap)
        float2 br0[4], br1[4];
        const float* bq0 = bp + (size_t)(qb + g) * S_LEN + kt * KT_N + tg * 2;
#pragma unroll
        for (int ni = 0; ni < 4; ++ni) {
            br0[ni] = *(const float2*)(bq0 + ni * 8);
            br1[ni] = *(const float2*)(bq0 + 8 * S_LEN + ni * 8);
        }

        // S = Q @ K^T  (warp: 16 q x 32 k), fp16 m16n8k16
        float s[4][4];
#pragma unroll
        for (int ni = 0; ni < 4; ++ni)
#pragma unroll
            for (int j = 0; j < 4; ++j) s[ni][j] = 0.0f;
        const char* Kcur = Kc[cur];
#pragma unroll
        for (int kcb = 0; kcb < 4; ++kcb) {
#pragma unroll
            for (int ni = 0; ni < 4; ++ni) {
                uint32_t bb[2];
                const char* kb2 = Kcur + (ni * 8 + g) * QPITCH
                                + (kcb * 16 + 2 * tg) * 2;
                bb[0] = *(const uint32_t*)(kb2);
                bb[1] = *(const uint32_t*)(kb2 + 16);
                mma_f16(s[ni], qf[kcb], bb);
            }
        }

        // mask + bias + exp; pack P to fp16 half2 (A-frag ready)
        uint32_t plo[4], phi[4];
#pragma unroll
        for (int ni = 0; ni < 4; ++ni) {
            const float p00 = fexp((s[ni][0] == 0.0f ? NEGV : s[ni][0]) + br0[ni].x);
            const float p01 = fexp((s[ni][1] == 0.0f ? NEGV : s[ni][1]) + br0[ni].y);
            const float p10 = fexp((s[ni][2] == 0.0f ? NEGV : s[ni][2]) + br1[ni].x);
            const float p11 = fexp((s[ni][3] == 0.0f ? NEGV : s[ni][3]) + br1[ni].y);
            l0 += p00 + p01;
            l1 += p10 + p11;
            __half2 hlo = __float22half2_rn(make_float2(p00, p01));
            __half2 hhi = __float22half2_rn(make_float2(p10, p11));
            plo[ni] = *(const uint32_t*)&hlo;
            phi[ni] = *(const uint32_t*)&hhi;
        }

        // acc += P @ V : fp16 m16n8k16, 2 k-blocks of 16 keys
        const char* Vcur = Vc[cur];
#pragma unroll
        for (int j = 0; j < 2; ++j) {
            uint32_t a[4];
            a[0] = plo[2 * j];
            a[1] = phi[2 * j];
            a[2] = plo[2 * j + 1];
            a[3] = phi[2 * j + 1];
#pragma unroll
            for (int ni = 0; ni < 8; ++ni) {
                uint32_t bb[2];
                const char* vb = Vcur + (ni * 8 + g) * VPITCH + (j * 16 + 2 * tg) * 2;
                bb[0] = *(const uint32_t*)(vb);
                bb[1] = *(const uint32_t*)(vb + 16);
                mma_f16(acc[ni], a, bb);
            }
        }

        if (kt + 1 < NTILES) {
            cpasync_wait0();
            __syncthreads();   // next tile resident; this tile's reads done
        }
    }

    // Row sums: single quad reduction at the end.
    l0 += __shfl_xor_sync(0xffffffffu, l0, 1);
    l0 += __shfl_xor_sync(0xffffffffu, l0, 2);
    l1 += __shfl_xor_sync(0xffffffffu, l1, 1);
    l1 += __shfl_xor_sync(0xffffffffu, l1, 2);

    // Epilogue: normalize, fp16 (O-proj A operand), store [b][s][hid]
    const float inv0 = 1.0f / l0;
    const float inv1 = 1.0f / l1;
#pragma unroll
    for (int ni = 0; ni < 8; ++ni) {
        const int col = h * DK + ni * 8 + tg * 2;
        __half* o0 = O + (size_t)(b * S_LEN + qrow0) * HID + col;
        __half* o1 = O + (size_t)(b * S_LEN + qrow0 + 8) * HID + col;
        *(__half2*)o0 = __float22half2_rn(
            make_float2(acc[ni][0] * inv0, acc[ni][1] * inv0));
        *(__half2*)o1 = __float22half2_rn(
            make_float2(acc[ni][2] * inv1, acc[ni][3] * inv1));
    }
}

// ---------------------------------------------------------------------------
extern "C" void kernel_launch(void* const* d_in, const int* in_sizes, int n_in,
                              void* d_out, int out_size)
{
    const float* batch = (const float*)d_in[0];
    const float* bias  = (const float*)d_in[1];
    const float* Wq = (const float*)d_in[2];
    const float* bq = (const float*)d_in[3];
    const float* Wk = (const float*)d_in[4];
    const float* bk = (const float*)d_in[5];
    const float* Wv = (const float*)d_in[6];
    const float* bv = (const float*)d_in[7];
    const float* Wo = (const float*)d_in[8];
    const float* bo = (const float*)d_in[9];
    float* out = (float*)d_out;

    __half *qptr, *kptr, *vtptr, *aptr, *xptr, *wqp, *wkp, *wvp, *wop;
    cudaGetSymbolAddress((void**)&qptr, g_q16);
    cudaGetSymbolAddress((void**)&kptr, g_k16);
    cudaGetSymbolAddress((void**)&vtptr, g_vt16);
    cudaGetSymbolAddress((void**)&aptr, g_att16);
    cudaGetSymbolAddress((void**)&xptr, g_x16);
    cudaGetSymbolAddress((void**)&wqp, g_wq16);
    cudaGetSymbolAddress((void**)&wkp, g_wk16);
    cudaGetSymbolAddress((void**)&wvp, g_wv16);
    cudaGetSymbolAddress((void**)&wop, g_wo16);

    static int attr_set = 0;
    if (!attr_set) {
        cudaFuncSetAttribute(gemm_qkv,
                             cudaFuncAttributeMaxDynamicSharedMemorySize,
                             GEMM_SMEM_BYTES);
        cudaFuncSetAttribute(gemm_o,
                             cudaFuncAttributeMaxDynamicSharedMemorySize,
                             GEMM_SMEM_BYTES);
        cudaFuncSetAttribute(attn_mma,
                             cudaFuncAttributeMaxDynamicSharedMemorySize,
                             ATTN_SMEM_BYTES);
        attr_set = 1;
    }

    const int totalG = G8X + 4 * G8W;
    round_all16<<<totalG / 256, 256>>>(
        (const float4*)batch, (const float4*)Wq, (const float4*)Wk,
        (const float4*)Wv, (const float4*)Wo,
        xptr, wqp, wkp, wvp, wop);

    dim3 qkvgrid(24, 32);
    gemm_qkv<<<qkvgrid, 256, GEMM_SMEM_BYTES>>>(xptr, wqp, wkp, wvp,
                                                bq, bk, bv, qptr, kptr, vtptr);

    dim3 agrid(S_LEN / 128, NH, BATCH);
    attn_mma<<<agrid, 256, ATTN_SMEM_BYTES>>>(qptr, kptr, vtptr, bias, aptr);

    dim3 ogrid(HID / 128, M_TOT / 128);
    gemm_o<<<ogrid, 256, GEMM_SMEM_BYTES>>>(aptr, wop, bo, out);
}

// round 13
// speedup vs baseline: 1.0060x; 1.0060x over previous
#include <cuda_runtime.h>
#include <cuda_fp16.h>
#include <cstdint>

// Problem constants
#define S_LEN  1024
#define HID    1024
#define NH     16
#define DK     64
#define BATCH  4
#define M_TOT  (BATCH * S_LEN)     // 4096
#define QK_SCALE 0.125f            // 64^-0.5
#define NEGV   (-9e15f)

// Scratch (static device globals — allocation-free per harness rules)
__device__ __align__(256) __half g_q16 [BATCH * NH * S_LEN * DK];  // [b][h][s][d], pre-scaled
__device__ __align__(256) __half g_k16 [BATCH * NH * S_LEN * DK];  // [b][h][s][d]
__device__ __align__(256) __half g_vt16[BATCH * NH * DK * S_LEN];  // [b][h][d][s]  (V^T)
__device__ __align__(256) __half g_att16[M_TOT * HID];             // attn out
__device__ __align__(256) __half g_x16 [M_TOT * HID];              // fp16 batch
__device__ __align__(256) __half g_wq16[HID * HID];
__device__ __align__(256) __half g_wk16[HID * HID];
__device__ __align__(256) __half g_wv16[HID * HID];
__device__ __align__(256) __half g_wo16[HID * HID];

__device__ __forceinline__ uint32_t smem_u32(const void* p) {
    uint32_t a;
    asm("{ .reg .u64 t; cvta.to.shared.u64 t, %1; cvt.u32.u64 %0, t; }"
        : "=r"(a) : "l"(p));
    return a;
}
__device__ __forceinline__ void cpasync16(uint32_t dst, const void* src) {
    asm volatile("cp.async.ca.shared.global [%0], [%1], 16;"
                 :: "r"(dst), "l"(src) : "memory");
}
__device__ __forceinline__ void cpasync_commit() {
    asm volatile("cp.async.commit_group;" ::: "memory");
}
__device__ __forceinline__ void cpasync_wait0() {
    asm volatile("cp.async.wait_group 0;" ::: "memory");
}
__device__ __forceinline__ void cpasync_wait1() {
    asm volatile("cp.async.wait_group 1;" ::: "memory");
}

// fp16 MMA, fp32 accumulate: D(16x8) += A(16x16) * B(16x8)
__device__ __forceinline__ void mma_f16(float c[4], const uint32_t a[4],
                                        const uint32_t b[2]) {
    asm volatile(
        "mma.sync.aligned.m16n8k16.row.col.f32.f16.f16.f32 "
        "{%0,%1,%2,%3}, {%4,%5,%6,%7}, {%8,%9}, {%0,%1,%2,%3};"
        : "+f"(c[0]), "+f"(c[1]), "+f"(c[2]), "+f"(c[3])
        : "r"(a[0]), "r"(a[1]), "r"(a[2]), "r"(a[3]),
          "r"(b[0]), "r"(b[1]));
}

// Fast exp on the FMA pipe. Rel err ~4e-5.
__device__ __forceinline__ float fexp(float x) {
    float z = x * 1.44269504f;
    z = fmaxf(z, -125.0f);
    const float C = 12582912.0f;            // 1.5 * 2^23
    float nf = z + C;
    int n = __float_as_int(nf) - 0x4B400000;
    float f = z - (nf - C);
    float p = 0.00961813f;
    p = fmaf(p, f, 0.0555041f);
    p = fmaf(p, f, 0.240227f);
    p = fmaf(p, f, 0.693147f);
    p = fmaf(p, f, 1.0f);
    return __int_as_float(__float_as_int(p) + (n << 23));
}

// ---------------------------------------------------------------------------
// Pre-round pass: batch + 4 weights -> fp16 scratch (single launch).
// ---------------------------------------------------------------------------
#define G8X (M_TOT * HID / 8)   // 524288
#define G8W (HID * HID / 8)     // 131072 = 2^17

__global__ __launch_bounds__(256) void round_all16(
    const float4* __restrict__ x,
    const float4* __restrict__ wq, const float4* __restrict__ wk,
    const float4* __restrict__ wv, const float4* __restrict__ wo,
    __half* __restrict__ ox,
    __half* __restrict__ owq, __half* __restrict__ owk,
    __half* __restrict__ owv, __half* __restrict__ owo)
{
    const int i = blockIdx.x * 256 + threadIdx.x;
    const float4* src;
    __half* dst;
    int off;
    if (i < G8X) {
        src = x; dst = ox; off = i;
    } else {
        const int j = i - G8X;
        const int sel = j >> 17;
        off = j & (G8W - 1);
        src = sel == 0 ? wq : (sel == 1 ? wk : (sel == 2 ? wv : wo));
        dst = sel == 0 ? owq : (sel == 1 ? owk : (sel == 2 ? owv : owo));
    }
    float4 v0 = src[off * 2];
    float4 v1 = src[off * 2 + 1];
    __half2 h[4];
    h[0] = __float22half2_rn(make_float2(v0.x, v0.y));
    h[1] = __float22half2_rn(make_float2(v0.z, v0.w));
    h[2] = __float22half2_rn(make_float2(v1.x, v1.y));
    h[3] = __float22half2_rn(make_float2(v1.z, v1.w));
    *(uint4*)(dst + (size_t)off * 8) = *(const uint4*)h;
}

// ---------------------------------------------------------------------------
// GEMM core: FP16 mma.sync (m16n8k16, fp32 accum), 128x128 tile, BK=32,
// 8 warps, 3-stage cp.async pipeline. Rows: 32 fp16, pitch 80 B.
// ---------------------------------------------------------------------------
#define PITCHB  80
#define TILEB   (128 * PITCHB)          // 10240 B per operand tile
#define STAGEB  (2 * TILEB)             // 20480
#define GEMM_SMEM_BYTES (3 * STAGEB)    // 61440

#define LOAD_STAGE(s, kk)                                                     \
    do {                                                                      \
        const uint32_t base = sbase + (uint32_t)(s) * STAGEB;                 \
        _Pragma("unroll")                                                     \
        for (int t = 0; t < 2; ++t) {                                         \
            const int idx = tid + t * 256;                                    \
            const int row = idx >> 2, c4 = idx & 3;                           \
            cpasync16(base + row * PITCHB + c4 * 16,                          \
                      Ap + (size_t)(bm + row) * 1024 + (kk) + c4 * 8);        \
            cpasync16(base + TILEB + row * PITCHB + c4 * 16,                  \
                      Wp + (size_t)(bn + row) * 1024 + (kk) + c4 * 8);        \
        }                                                                     \
        cpasync_commit();                                                     \
    } while (0)

#define GEMM_MAINLOOP16()                                                     \
    LOAD_STAGE(0, 0);                                                         \
    LOAD_STAGE(1, 32);                                                        \
    for (int i = 0; i < 32; ++i) {                                            \
        if (i >= 30) cpasync_wait0(); else cpasync_wait1();                   \
        __syncthreads();                                                      \
        if (i + 2 < 32) {                                                     \
            const int s2 = (i + 2) % 3;                                       \
            LOAD_STAGE(s2, (i + 2) * 32);                                     \
        }                                                                     \
        const char* Sb = (const char*)sm + (i % 3) * STAGEB;                  \
        _Pragma("unroll")                                                     \
        for (int ks = 0; ks < 2; ++ks) {                                      \
            const int kbB = ks * 32;                                          \
            uint32_t af[2][4];                                                \
            _Pragma("unroll")                                                 \
            for (int mi = 0; mi < 2; ++mi) {                                  \
                const char* p = Sb + (wm * 32 + mi * 16 + g) * PITCHB         \
                                + kbB + tg * 4;                               \
                af[mi][0] = *(const uint32_t*)(p);                            \
                af[mi][1] = *(const uint32_t*)(p + 8 * PITCHB);               \
                af[mi][2] = *(const uint32_t*)(p + 16);                       \
                af[mi][3] = *(const uint32_t*)(p + 8 * PITCHB + 16);          \
            }                                                                 \
            uint32_t bf[8][2];                                                \
            _Pragma("unroll")                                                 \
            for (int ni = 0; ni < 8; ++ni) {                                  \
                const char* p = Sb + TILEB + (wn * 64 + ni * 8 + g) * PITCHB  \
                                + kbB + tg * 4;                               \
                bf[ni][0] = *(const uint32_t*)(p);                            \
                bf[ni][1] = *(const uint32_t*)(p + 16);                       \
            }                                                                 \
            _Pragma("unroll")                                                 \
            for (int mi = 0; mi < 2; ++mi)                                    \
                _Pragma("unroll")                                             \
                for (int ni = 0; ni < 8; ++ni)                                \
                    mma_f16(c[mi][ni], af[mi], bf[ni]);                       \
        }                                                                     \
    }

// Fused QKV projection: grid (24, 32); bx>>3 selects {Q,K,V}.
__global__ __launch_bounds__(256, 2) void gemm_qkv(
    const __half* __restrict__ A,
    const __half* __restrict__ Wqp, const __half* __restrict__ Wkp,
    const __half* __restrict__ Wvp,
    const float* __restrict__ bq, const float* __restrict__ bk,
    const float* __restrict__ bv,
    __half* __restrict__ oq, __half* __restrict__ ok, __half* __restrict__ ovt)
{
    extern __shared__ float sm[];
    const uint32_t sbase = smem_u32(sm);

    const int tid = threadIdx.x;
    const int wid = tid >> 5, lid = tid & 31;
    const int which = blockIdx.x >> 3;
    const int bn = (blockIdx.x & 7) * 128;
    const int bm = blockIdx.y * 128;
    const int wm = wid >> 1, wn = wid & 1;
    const int g = lid >> 2, tg = lid & 3;

    const __half* Wp  = which == 0 ? Wqp : (which == 1 ? Wkp : Wvp);
    const float* bias = which == 0 ? bq  : (which == 1 ? bk  : bv);
    const __half* Ap = A;

    float c[2][8][4];
#pragma unroll
    for (int mi = 0; mi < 2; ++mi)
#pragma unroll
        for (int ni = 0; ni < 8; ++ni)
#pragma unroll
            for (int k = 0; k < 4; ++k) c[mi][ni][k] = 0.0f;

    GEMM_MAINLOOP16();

    if (which < 2) {
        __half* out = which == 0 ? oq : ok;
        const float scale = which == 0 ? QK_SCALE : 1.0f;
#pragma unroll
        for (int mi = 0; mi < 2; ++mi) {
            const int rowa = bm + wm * 32 + mi * 16 + g;
            const int rowb = rowa + 8;
#pragma unroll
            for (int ni = 0; ni < 8; ++ni) {
                const int col = bn + wn * 64 + ni * 8 + tg * 2;
                const float b0 = bias[col], b1 = bias[col + 1];
                __half2 h0 = __float22half2_rn(
                    make_float2((c[mi][ni][0] + b0) * scale,
                                (c[mi][ni][1] + b1) * scale));
                __half2 h1 = __float22half2_rn(
                    make_float2((c[mi][ni][2] + b0) * scale,
                                (c[mi][ni][3] + b1) * scale));
                const int h = col >> 6, d = col & 63;
                const int ba = rowa >> 10, sa = rowa & 1023;
                const int bb = rowb >> 10, sb2 = rowb & 1023;
                *(__half2*)(out + (((size_t)(ba * NH + h) * S_LEN + sa) * DK + d)) = h0;
                *(__half2*)(out + (((size_t)(bb * NH + h) * S_LEN + sb2) * DK + d)) = h1;
            }
        }
    } else {
        // V: stage transposed [n][m] fp16 tile (pitch 136 halfs)
        __syncthreads();
        __half* st = (__half*)sm;
#pragma unroll
        for (int mi = 0; mi < 2; ++mi) {
            const int ma = wm * 32 + mi * 16 + g;
            const int mb = ma + 8;
#pragma unroll
            for (int ni = 0; ni < 8; ++ni) {
                const int nl = wn * 64 + ni * 8 + tg * 2;
                const float b0 = bias[bn + nl], b1 = bias[bn + nl + 1];
                st[(nl + 0) * 136 + ma] = __float2half_rn(c[mi][ni][0] + b0);
                st[(nl + 1) * 136 + ma] = __float2half_rn(c[mi][ni][1] + b1);
                st[(nl + 0) * 136 + mb] = __float2half_rn(c[mi][ni][2] + b0);
                st[(nl + 1) * 136 + mb] = __float2half_rn(c[mi][ni][3] + b1);
            }
        }
        __syncthreads();
        const int r = tid >> 1, sel = tid & 1;
        const int col = bn + r;
        const int hh = col >> 6, d = col & 63;
        const int bb2 = bm >> 10;
        const int s0 = (bm & 1023) + sel * 64;
        __half* dst = ovt + (((size_t)(bb2 * NH + hh) * DK + d) * S_LEN + s0);
        const __half* srcp = st + r * 136 + sel * 64;
#pragma unroll
        for (int k2 = 0; k2 < 8; ++k2)
            *(uint4*)(dst + k2 * 8) = *(const uint4*)(srcp + k2 * 8);
    }
}

// Output projection: fp16 inputs, row-major fp32 out.
__global__ __launch_bounds__(256, 2) void gemm_o(
    const __half* __restrict__ A, const __half* __restrict__ W,
    const float* __restrict__ bias, float* __restrict__ out)
{
    extern __shared__ float sm[];
    const uint32_t sbase = smem_u32(sm);

    const int tid = threadIdx.x;
    const int wid = tid >> 5, lid = tid & 31;
    const int bn = blockIdx.x * 128;
    const int bm = blockIdx.y * 128;
    const int wm = wid >> 1, wn = wid & 1;
    const int g = lid >> 2, tg = lid & 3;
    const __half* Ap = A;
    const __half* Wp = W;

    float c[2][8][4];
#pragma unroll
    for (int mi = 0; mi < 2; ++mi)
#pragma unroll
        for (int ni = 0; ni < 8; ++ni)
#pragma unroll
            for (int k = 0; k < 4; ++k) c[mi][ni][k] = 0.0f;

    GEMM_MAINLOOP16();

#pragma unroll
    for (int mi = 0; mi < 2; ++mi) {
        const int rowa = bm + wm * 32 + mi * 16 + g;
        const int rowb = rowa + 8;
#pragma unroll
        for (int ni = 0; ni < 8; ++ni) {
            const int col = bn + wn * 64 + ni * 8 + tg * 2;
            const float b0 = bias[col], b1 = bias[col + 1];
            *(float2*)(out + (size_t)rowa * HID + col) =
                make_float2(c[mi][ni][0] + b0, c[mi][ni][1] + b1);
            *(float2*)(out + (size_t)rowb * HID + col) =
                make_float2(c[mi][ni][2] + b0, c[mi][ni][3] + b1);
        }
    }
}

// ---------------------------------------------------------------------------
// FP16 tensor-core flash attention. K-tiles of 32. Fixed-zero-max softmax.
// Q fragments hoisted to registers (loaded once from smem, pre-loop).
// Bias staged via cp.async (double-buffered, one tile lookahead) — the
// combination R11 proved (bias latency) + R12's good half (Q crossbar).
// CTA: 128 q, 8 warps x 16 q-rows.
// Smem bytes: Q[128x144] | K0,K1[32x144] | Vt0,Vt1[64x80] | B0,B1[128x144]
// ---------------------------------------------------------------------------
#define QPITCH 144
#define VPITCH 80
#define BPADF  36                                  // floats (144 B)
#define QS_B   0
#define K0_B   (128 * QPITCH)                      // 18432
#define K1_B   (K0_B + 32 * QPITCH)                // 23040
#define V0_B   (K1_B + 32 * QPITCH)                // 27648
#define V1_B   (V0_B + 64 * VPITCH)                // 32768
#define B0_B   (V1_B + 64 * VPITCH)                // 37888
#define B1_B   (B0_B + 128 * BPADF * 4)            // 56320
#define ATTN_SMEM_BYTES (B1_B + 128 * BPADF * 4)   // 74752

#define KT_N   32
#define NTILES (S_LEN / KT_N)                      // 32

__global__ __launch_bounds__(256, 2) void attn_mma(
    const __half* __restrict__ Qg, const __half* __restrict__ Kg,
    const __half* __restrict__ Vt, const float* __restrict__ Bias,
    __half* __restrict__ O)
{
    extern __shared__ float sm[];
    char* smc = (char*)sm;
    const uint32_t sb = smem_u32(sm);
    const uint32_t KbB[2] = { sb + K0_B, sb + K1_B };
    const uint32_t VbB[2] = { sb + V0_B, sb + V1_B };
    const uint32_t BbB[2] = { sb + B0_B, sb + B1_B };
    const char* Kc[2] = { smc + K0_B, smc + K1_B };
    const char* Vc[2] = { smc + V0_B, smc + V1_B };
    const float* Bf[2] = { (const float*)(smc + B0_B), (const float*)(smc + B1_B) };

    const int q0 = blockIdx.x * 128;
    const int h  = blockIdx.y;
    const int b  = blockIdx.z;
    const int bh = b * NH + h;

    const __half* qp = Qg + (size_t)bh * S_LEN * DK + (size_t)q0 * DK;
    const __half* kp = Kg + (size_t)bh * S_LEN * DK;
    const __half* vtp = Vt + (size_t)bh * DK * S_LEN;
    const float* bp = Bias + (size_t)bh * S_LEN * S_LEN + (size_t)q0 * S_LEN;

    const int tid = threadIdx.x;
    const int wid = tid >> 5, lid = tid & 31;
    const int g = lid >> 2, tg = lid & 3;
    const int qb = wid * 16;
    const int qrow0 = q0 + qb + g;

    // Per-tile async loads: K 32x64 fp16, Vt 64x32 fp16, bias 128x32 fp32.
#define LOAD_TILE(st, kt)                                                     \
    do {                                                                      \
        {                                                                     \
            const int row = tid >> 3, off = tid & 7;                          \
            cpasync16(KbB[st] + row * QPITCH + off * 16,                      \
                      kp + (size_t)((kt) * KT_N + row) * 64 + off * 8);       \
        }                                                                     \
        {                                                                     \
            const int row = tid >> 2, off = tid & 3;                          \
            cpasync16(VbB[st] + row * VPITCH + off * 16,                      \
                      vtp + (size_t)row * S_LEN + (kt) * KT_N + off * 8);     \
        }                                                                     \
        const float* bpn = bp + (kt) * KT_N;                                  \
        _Pragma("unroll")                                                     \
        for (int i2 = 0; i2 < 4; ++i2) {                                      \
            const int cidx = tid + i2 * 256;                                  \
            const int row = cidx >> 3, off = cidx & 7;                        \
            cpasync16(BbB[st] + row * (BPADF * 4) + off * 16,                 \
                      bpn + (size_t)row * S_LEN + off * 4);                   \
        }                                                                     \
        cpasync_commit();                                                     \
    } while (0)

    // Prologue: Q tile + tile 0 in one group, then wait and hoist Q.
#pragma unroll
    for (int i = 0; i < 4; ++i) {
        const int cidx = tid + i * 256;
        const int row = cidx >> 3, off = cidx & 7;
        cpasync16(sb + QS_B + row * QPITCH + off * 16, qp + row * 64 + off * 8);
    }
    LOAD_TILE(0, 0);
    cpasync_wait0();
    __syncthreads();

    // Hoist Q fragments into registers (tile-invariant).
    uint32_t qf[4][4];
#pragma unroll
    for (int kcb = 0; kcb < 4; ++kcb) {
        const char* qa = smc + QS_B + (qb + g) * QPITCH + (kcb * 16 + 2 * tg) * 2;
        qf[kcb][0] = *(const uint32_t*)(qa);
        qf[kcb][1] = *(const uint32_t*)(qa + 8 * QPITCH);
        qf[kcb][2] = *(const uint32_t*)(qa + 16);
        qf[kcb][3] = *(const uint32_t*)(qa + 8 * QPITCH + 16);
    }

    float l0 = 0.0f, l1 = 0.0f;
    float acc[8][4];
#pragma unroll
    for (int ni = 0; ni < 8; ++ni)
#pragma unroll
        for (int j = 0; j < 4; ++j) acc[ni][j] = 0.0f;

    for (int kt = 0; kt < NTILES; ++kt) {
        const int cur = kt & 1;
        if (kt + 1 < NTILES) LOAD_TILE(cur ^ 1, kt + 1);

        // S = Q @ K^T  (warp: 16 q x 32 k), fp16 m16n8k16
        float s[4][4];
#pragma unroll
        for (int ni = 0; ni < 4; ++ni)
#pragma unroll
            for (int j = 0; j < 4; ++j) s[ni][j] = 0.0f;
        const char* Kcur = Kc[cur];
#pragma unroll
        for (int kcb = 0; kcb < 4; ++kcb) {
#pragma unroll
            for (int ni = 0; ni < 4; ++ni) {
                uint32_t bb[2];
                const char* kb2 = Kcur + (ni * 8 + g) * QPITCH
                                + (kcb * 16 + 2 * tg) * 2;
                bb[0] = *(const uint32_t*)(kb2);
                bb[1] = *(const uint32_t*)(kb2 + 16);
                mma_f16(s[ni], qf[kcb], bb);
            }
        }

        // mask + bias (from staged smem) + exp; pack P to fp16 (A-frag ready)
        const float* Bcur = Bf[cur];
        uint32_t plo[4], phi[4];
#pragma unroll
        for (int ni = 0; ni < 4; ++ni) {
            const int bco = ni * 8 + tg * 2;
            float2 b0 = *(const float2*)(Bcur + (qb + g) * BPADF + bco);
            float2 b1 = *(const float2*)(Bcur + (qb + g + 8) * BPADF + bco);
            const float p00 = fexp((s[ni][0] == 0.0f ? NEGV : s[ni][0]) + b0.x);
            const float p01 = fexp((s[ni][1] == 0.0f ? NEGV : s[ni][1]) + b0.y);
            const float p10 = fexp((s[ni][2] == 0.0f ? NEGV : s[ni][2]) + b1.x);
            const float p11 = fexp((s[ni][3] == 0.0f ? NEGV : s[ni][3]) + b1.y);
            l0 += p00 + p01;
            l1 += p10 + p11;
            __half2 hlo = __float22half2_rn(make_float2(p00, p01));
            __half2 hhi = __float22half2_rn(make_float2(p10, p11));
            plo[ni] = *(const uint32_t*)&hlo;
            phi[ni] = *(const uint32_t*)&hhi;
        }

        // acc += P @ V : fp16 m16n8k16, 2 k-blocks of 16 keys
        const char* Vcur = Vc[cur];
#pragma unroll
        for (int j = 0; j < 2; ++j) {
            uint32_t a[4];
            a[0] = plo[2 * j];
            a[1] = phi[2 * j];
            a[2] = plo[2 * j + 1];
            a[3] = phi[2 * j + 1];
#pragma unroll
            for (int ni = 0; ni < 8; ++ni) {
                uint32_t bb[2];
                const char* vb = Vcur + (ni * 8 + g) * VPITCH + (j * 16 + 2 * tg) * 2;
                bb[0] = *(const uint32_t*)(vb);
                bb[1] = *(const uint32_t*)(vb + 16);
                mma_f16(acc[ni], a, bb);
            }
        }

        if (kt + 1 < NTILES) {
            cpasync_wait0();
            __syncthreads();   // next tile resident; this tile's reads done
        }
    }

    // Row sums: single quad reduction at the end.
    l0 += __shfl_xor_sync(0xffffffffu, l0, 1);
    l0 += __shfl_xor_sync(0xffffffffu, l0, 2);
    l1 += __shfl_xor_sync(0xffffffffu, l1, 1);
    l1 += __shfl_xor_sync(0xffffffffu, l1, 2);

    // Epilogue: normalize, fp16 (O-proj A operand), store [b][s][hid]
    const float inv0 = 1.0f / l0;
    const float inv1 = 1.0f / l1;
#pragma unroll
    for (int ni = 0; ni < 8; ++ni) {
        const int col = h * DK + ni * 8 + tg * 2;
        __half* o0 = O + (size_t)(b * S_LEN + qrow0) * HID + col;
        __half* o1 = O + (size_t)(b * S_LEN + qrow0 + 8) * HID + col;
        *(__half2*)o0 = __float22half2_rn(
            make_float2(acc[ni][0] * inv0, acc[ni][1] * inv0));
        *(__half2*)o1 = __float22half2_rn(
            make_float2(acc[ni][2] * inv1, acc[ni][3] * inv1));
    }
}

// ---------------------------------------------------------------------------
extern "C" void kernel_launch(void* const* d_in, const int* in_sizes, int n_in,
                              void* d_out, int out_size)
{
    const float* batch = (const float*)d_in[0];
    const float* bias  = (const float*)d_in[1];
    const float* Wq = (const float*)d_in[2];
    const float* bq = (const float*)d_in[3];
    const float* Wk = (const float*)d_in[4];
    const float* bk = (const float*)d_in[5];
    const float* Wv = (const float*)d_in[6];
    const float* bv = (const float*)d_in[7];
    const float* Wo = (const float*)d_in[8];
    const float* bo = (const float*)d_in[9];
    float* out = (float*)d_out;

    __half *qptr, *kptr, *vtptr, *aptr, *xptr, *wqp, *wkp, *wvp, *wop;
    cudaGetSymbolAddress((void**)&qptr, g_q16);
    cudaGetSymbolAddress((void**)&kptr, g_k16);
    cudaGetSymbolAddress((void**)&vtptr, g_vt16);
    cudaGetSymbolAddress((void**)&aptr, g_att16);
    cudaGetSymbolAddress((void**)&xptr, g_x16);
    cudaGetSymbolAddress((void**)&wqp, g_wq16);
    cudaGetSymbolAddress((void**)&wkp, g_wk16);
    cudaGetSymbolAddress((void**)&wvp, g_wv16);
    cudaGetSymbolAddress((void**)&wop, g_wo16);

    static int attr_set = 0;
    if (!attr_set) {
        cudaFuncSetAttribute(gemm_qkv,
                             cudaFuncAttributeMaxDynamicSharedMemorySize,
                             GEMM_SMEM_BYTES);
        cudaFuncSetAttribute(gemm_o,
                             cudaFuncAttributeMaxDynamicSharedMemorySize,
                             GEMM_SMEM_BYTES);
        cudaFuncSetAttribute(attn_mma,
                             cudaFuncAttributeMaxDynamicSharedMemorySize,
                             ATTN_SMEM_BYTES);
        attr_set = 1;
    }

    const int totalG = G8X + 4 * G8W;
    round_all16<<<totalG / 256, 256>>>(
        (const float4*)batch, (const float4*)Wq, (const float4*)Wk,
        (const float4*)Wv, (const float4*)Wo,
        xptr, wqp, wkp, wvp, wop);

    dim3 qkvgrid(24, 32);
    gemm_qkv<<<qkvgrid, 256, GEMM_SMEM_BYTES>>>(xptr, wqp, wkp, wvp,
                                                bq, bk, bv, qptr, kptr, vtptr);

    dim3 agrid(S_LEN / 128, NH, BATCH);
    attn_mma<<<agrid, 256, ATTN_SMEM_BYTES>>>(qptr, kptr, vtptr, bias, aptr);

    dim3 ogrid(HID / 128, M_TOT / 128);
    gemm_o<<<ogrid, 256, GEMM_SMEM_BYTES>>>(aptr, wop, bo, out);
}

// round 15
// speedup vs baseline: 1.0600x; 1.0537x over previous
#include <cuda_runtime.h>
#include <cuda_fp16.h>
#include <cstdint>

// Problem constants
#define S_LEN  1024
#define HID    1024
#define NH     16
#define DK     64
#define BATCH  4
#define M_TOT  (BATCH * S_LEN)     // 4096
#define QK_SCALE 0.125f            // 64^-0.5
#define NEGV   (-9e15f)

// Scratch (static device globals — allocation-free per harness rules)
__device__ __align__(256) __half g_q16 [BATCH * NH * S_LEN * DK];  // [b][h][s][d], pre-scaled
__device__ __align__(256) __half g_k16 [BATCH * NH * S_LEN * DK];  // [b][h][s][d]
__device__ __align__(256) __half g_vt16[BATCH * NH * DK * S_LEN];  // [b][h][d][s]  (V^T)
__device__ __align__(256) __half g_att16[M_TOT * HID];             // attn out
__device__ __align__(256) __half g_x16 [M_TOT * HID];              // fp16 batch
__device__ __align__(256) __half g_wq16[HID * HID];
__device__ __align__(256) __half g_wk16[HID * HID];
__device__ __align__(256) __half g_wv16[HID * HID];
__device__ __align__(256) __half g_wo16[HID * HID];

__device__ __forceinline__ uint32_t smem_u32(const void* p) {
    uint32_t a;
    asm("{ .reg .u64 t; cvta.to.shared.u64 t, %1; cvt.u32.u64 %0, t; }"
        : "=r"(a) : "l"(p));
    return a;
}
__device__ __forceinline__ void cpasync16(uint32_t dst, const void* src) {
    asm volatile("cp.async.ca.shared.global [%0], [%1], 16;"
                 :: "r"(dst), "l"(src) : "memory");
}
__device__ __forceinline__ void cpasync_commit() {
    asm volatile("cp.async.commit_group;" ::: "memory");
}
__device__ __forceinline__ void cpasync_wait0() {
    asm volatile("cp.async.wait_group 0;" ::: "memory");
}
__device__ __forceinline__ void cpasync_wait1() {
    asm volatile("cp.async.wait_group 1;" ::: "memory");
}

// fp16 MMA, fp32 accumulate: D(16x8) += A(16x16) * B(16x8)
__device__ __forceinline__ void mma_f16(float c[4], const uint32_t a[4],
                                        const uint32_t b[2]) {
    asm volatile(
        "mma.sync.aligned.m16n8k16.row.col.f32.f16.f16.f32 "
        "{%0,%1,%2,%3}, {%4,%5,%6,%7}, {%8,%9}, {%0,%1,%2,%3};"
        : "+f"(c[0]), "+f"(c[1]), "+f"(c[2]), "+f"(c[3])
        : "r"(a[0]), "r"(a[1]), "r"(a[2]), "r"(a[3]),
          "r"(b[0]), "r"(b[1]));
}

// Fast exp on the FMA pipe. Rel err ~4e-5.
__device__ __forceinline__ float fexp(float x) {
    float z = x * 1.44269504f;
    z = fmaxf(z, -125.0f);
    const float C = 12582912.0f;            // 1.5 * 2^23
    float nf = z + C;
    int n = __float_as_int(nf) - 0x4B400000;
    float f = z - (nf - C);
    float p = 0.00961813f;
    p = fmaf(p, f, 0.0555041f);
    p = fmaf(p, f, 0.240227f);
    p = fmaf(p, f, 0.693147f);
    p = fmaf(p, f, 1.0f);
    return __int_as_float(__float_as_int(p) + (n << 23));
}

// ---------------------------------------------------------------------------
// Pre-round pass: batch + 4 weights -> fp16 scratch (single launch).
// ---------------------------------------------------------------------------
#define G8X (M_TOT * HID / 8)   // 524288
#define G8W (HID * HID / 8)     // 131072 = 2^17

__global__ __launch_bounds__(256) void round_all16(
    const float4* __restrict__ x,
    const float4* __restrict__ wq, const float4* __restrict__ wk,
    const float4* __restrict__ wv, const float4* __restrict__ wo,
    __half* __restrict__ ox,
    __half* __restrict__ owq, __half* __restrict__ owk,
    __half* __restrict__ owv, __half* __restrict__ owo)
{
    const int i = blockIdx.x * 256 + threadIdx.x;
    const float4* src;
    __half* dst;
    int off;
    if (i < G8X) {
        src = x; dst = ox; off = i;
    } else {
        const int j = i - G8X;
        const int sel = j >> 17;
        off = j & (G8W - 1);
        src = sel == 0 ? wq : (sel == 1 ? wk : (sel == 2 ? wv : wo));
        dst = sel == 0 ? owq : (sel == 1 ? owk : (sel == 2 ? owv : owo));
    }
    float4 v0 = src[off * 2];
    float4 v1 = src[off * 2 + 1];
    __half2 h[4];
    h[0] = __float22half2_rn(make_float2(v0.x, v0.y));
    h[1] = __float22half2_rn(make_float2(v0.z, v0.w));
    h[2] = __float22half2_rn(make_float2(v1.x, v1.y));
    h[3] = __float22half2_rn(make_float2(v1.z, v1.w));
    *(uint4*)(dst + (size_t)off * 8) = *(const uint4*)h;
}

// ---------------------------------------------------------------------------
// GEMM core: FP16 mma.sync (m16n8k16, fp32 accum), 128x128 tile, BK=32,
// 8 warps, 3-stage cp.async pipeline. Rows: 32 fp16, pitch 80 B.
// ---------------------------------------------------------------------------
#define PITCHB  80
#define TILEB   (128 * PITCHB)          // 10240 B per operand tile
#define STAGEB  (2 * TILEB)             // 20480
#define GEMM_SMEM_BYTES (3 * STAGEB)    // 61440

#define LOAD_STAGE(s, kk)                                                     \
    do {                                                                      \
        const uint32_t base = sbase + (uint32_t)(s) * STAGEB;                 \
        _Pragma("unroll")                                                     \
        for (int t = 0; t < 2; ++t) {                                         \
            const int idx = tid + t * 256;                                    \
            const int row = idx >> 2, c4 = idx & 3;                           \
            cpasync16(base + row * PITCHB + c4 * 16,                          \
                      Ap + (size_t)(bm + row) * 1024 + (kk) + c4 * 8);        \
            cpasync16(base + TILEB + row * PITCHB + c4 * 16,                  \
                      Wp + (size_t)(bn + row) * 1024 + (kk) + c4 * 8);        \
        }                                                                     \
        cpasync_commit();                                                     \
    } while (0)

#define GEMM_MAINLOOP16()                                                     \
    LOAD_STAGE(0, 0);                                                         \
    LOAD_STAGE(1, 32);                                                        \
    for (int i = 0; i < 32; ++i) {                                            \
        if (i >= 30) cpasync_wait0(); else cpasync_wait1();                   \
        __syncthreads();                                                      \
        if (i + 2 < 32) {                                                     \
            const int s2 = (i + 2) % 3;                                       \
            LOAD_STAGE(s2, (i + 2) * 32);                                     \
        }                                                                     \
        const char* Sb = (const char*)sm + (i % 3) * STAGEB;                  \
        _Pragma("unroll")                                                     \
        for (int ks = 0; ks < 2; ++ks) {                                      \
            const int kbB = ks * 32;                                          \
            uint32_t af[2][4];                                                \
            _Pragma("unroll")                                                 \
            for (int mi = 0; mi < 2; ++mi) {                                  \
                const char* p = Sb + (wm * 32 + mi * 16 + g) * PITCHB         \
                                + kbB + tg * 4;                               \
                af[mi][0] = *(const uint32_t*)(p);                            \
                af[mi][1] = *(const uint32_t*)(p + 8 * PITCHB);               \
                af[mi][2] = *(const uint32_t*)(p + 16);                       \
                af[mi][3] = *(const uint32_t*)(p + 8 * PITCHB + 16);          \
            }                                                                 \
            uint32_t bf[8][2];                                                \
            _Pragma("unroll")                                                 \
            for (int ni = 0; ni < 8; ++ni) {                                  \
                const char* p = Sb + TILEB + (wn * 64 + ni * 8 + g) * PITCHB  \
                                + kbB + tg * 4;                               \
                bf[ni][0] = *(const uint32_t*)(p);                            \
                bf[ni][1] = *(const uint32_t*)(p + 16);                       \
            }                                                                 \
            _Pragma("unroll")                                                 \
            for (int mi = 0; mi < 2; ++mi)                                    \
                _Pragma("unroll")                                             \
                for (int ni = 0; ni < 8; ++ni)                                \
                    mma_f16(c[mi][ni], af[mi], bf[ni]);                       \
        }                                                                     \
    }

// Fused QKV projection: grid (24, 32); bx>>3 selects {Q,K,V}.
__global__ __launch_bounds__(256, 2) void gemm_qkv(
    const __half* __restrict__ A,
    const __half* __restrict__ Wqp, const __half* __restrict__ Wkp,
    const __half* __restrict__ Wvp,
    const float* __restrict__ bq, const float* __restrict__ bk,
    const float* __restrict__ bv,
    __half* __restrict__ oq, __half* __restrict__ ok, __half* __restrict__ ovt)
{
    extern __shared__ float sm[];
    const uint32_t sbase = smem_u32(sm);

    const int tid = threadIdx.x;
    const int wid = tid >> 5, lid = tid & 31;
    const int which = blockIdx.x >> 3;
    const int bn = (blockIdx.x & 7) * 128;
    const int bm = blockIdx.y * 128;
    const int wm = wid >> 1, wn = wid & 1;
    const int g = lid >> 2, tg = lid & 3;

    const __half* Wp  = which == 0 ? Wqp : (which == 1 ? Wkp : Wvp);
    const float* bias = which == 0 ? bq  : (which == 1 ? bk  : bv);
    const __half* Ap = A;

    float c[2][8][4];
#pragma unroll
    for (int mi = 0; mi < 2; ++mi)
#pragma unroll
        for (int ni = 0; ni < 8; ++ni)
#pragma unroll
            for (int k = 0; k < 4; ++k) c[mi][ni][k] = 0.0f;

    GEMM_MAINLOOP16();

    if (which < 2) {
        __half* out = which == 0 ? oq : ok;
        const float scale = which == 0 ? QK_SCALE : 1.0f;
#pragma unroll
        for (int mi = 0; mi < 2; ++mi) {
            const int rowa = bm + wm * 32 + mi * 16 + g;
            const int rowb = rowa + 8;
#pragma unroll
            for (int ni = 0; ni < 8; ++ni) {
                const int col = bn + wn * 64 + ni * 8 + tg * 2;
                const float b0 = bias[col], b1 = bias[col + 1];
                __half2 h0 = __float22half2_rn(
                    make_float2((c[mi][ni][0] + b0) * scale,
                                (c[mi][ni][1] + b1) * scale));
                __half2 h1 = __float22half2_rn(
                    make_float2((c[mi][ni][2] + b0) * scale,
                                (c[mi][ni][3] + b1) * scale));
                const int h = col >> 6, d = col & 63;
                const int ba = rowa >> 10, sa = rowa & 1023;
                const int bb = rowb >> 10, sb2 = rowb & 1023;
                *(__half2*)(out + (((size_t)(ba * NH + h) * S_LEN + sa) * DK + d)) = h0;
                *(__half2*)(out + (((size_t)(bb * NH + h) * S_LEN + sb2) * DK + d)) = h1;
            }
        }
    } else {
        // V: stage transposed [n][m] fp16 tile (pitch 136 halfs)
        __syncthreads();
        __half* st = (__half*)sm;
#pragma unroll
        for (int mi = 0; mi < 2; ++mi) {
            const int ma = wm * 32 + mi * 16 + g;
            const int mb = ma + 8;
#pragma unroll
            for (int ni = 0; ni < 8; ++ni) {
                const int nl = wn * 64 + ni * 8 + tg * 2;
                const float b0 = bias[bn + nl], b1 = bias[bn + nl + 1];
                st[(nl + 0) * 136 + ma] = __float2half_rn(c[mi][ni][0] + b0);
                st[(nl + 1) * 136 + ma] = __float2half_rn(c[mi][ni][1] + b1);
                st[(nl + 0) * 136 + mb] = __float2half_rn(c[mi][ni][2] + b0);
                st[(nl + 1) * 136 + mb] = __float2half_rn(c[mi][ni][3] + b1);
            }
        }
        __syncthreads();
        const int r = tid >> 1, sel = tid & 1;
        const int col = bn + r;
        const int hh = col >> 6, d = col & 63;
        const int bb2 = bm >> 10;
        const int s0 = (bm & 1023) + sel * 64;
        __half* dst = ovt + (((size_t)(bb2 * NH + hh) * DK + d) * S_LEN + s0);
        const __half* srcp = st + r * 136 + sel * 64;
#pragma unroll
        for (int k2 = 0; k2 < 8; ++k2)
            *(uint4*)(dst + k2 * 8) = *(const uint4*)(srcp + k2 * 8);
    }
}

// Output projection: fp16 inputs, row-major fp32 out.
__global__ __launch_bounds__(256, 2) void gemm_o(
    const __half* __restrict__ A, const __half* __restrict__ W,
    const float* __restrict__ bias, float* __restrict__ out)
{
    extern __shared__ float sm[];
    const uint32_t sbase = smem_u32(sm);

    const int tid = threadIdx.x;
    const int wid = tid >> 5, lid = tid & 31;
    const int bn = blockIdx.x * 128;
    const int bm = blockIdx.y * 128;
    const int wm = wid >> 1, wn = wid & 1;
    const int g = lid >> 2, tg = lid & 3;
    const __half* Ap = A;
    const __half* Wp = W;

    float c[2][8][4];
#pragma unroll
    for (int mi = 0; mi < 2; ++mi)
#pragma unroll
        for (int ni = 0; ni < 8; ++ni)
#pragma unroll
            for (int k = 0; k < 4; ++k) c[mi][ni][k] = 0.0f;

    GEMM_MAINLOOP16();

#pragma unroll
    for (int mi = 0; mi < 2; ++mi) {
        const int rowa = bm + wm * 32 + mi * 16 + g;
        const int rowb = rowa + 8;
#pragma unroll
        for (int ni = 0; ni < 8; ++ni) {
            const int col = bn + wn * 64 + ni * 8 + tg * 2;
            const float b0 = bias[col], b1 = bias[col + 1];
            *(float2*)(out + (size_t)rowa * HID + col) =
                make_float2(c[mi][ni][0] + b0, c[mi][ni][1] + b1);
            *(float2*)(out + (size_t)rowb * HID + col) =
                make_float2(c[mi][ni][2] + b0, c[mi][ni][3] + b1);
        }
    }
}

// ---------------------------------------------------------------------------
// FP16 tensor-core flash attention. K-tiles of 32. Fixed-zero-max softmax.
// R11 compute body (Q frags from smem, bias staged) + 3-STAGE cp.async ring
// on K/V/bias with two-tile lookahead (wait_group 1).
// CTA: 128 q, 8 warps x 16 q-rows.
// Stage: K[32x144] + Vt[64x80] + B[128x144] = 28160 B; 3 stages + Q = 102912
// ---------------------------------------------------------------------------
#define QPITCH 144
#define VPITCH 80
#define BPADF  36                                  // floats (144 B)
#define QS_B   0
#define STG_K  0
#define STG_V  (32 * QPITCH)                       // 4608
#define STG_BI (STG_V + 64 * VPITCH)               // 9728
#define STG_SZ (STG_BI + 128 * BPADF * 4)          // 28160
#define STG0_B (128 * QPITCH)                      // 18432 (after Q)
#define ATTN_SMEM_BYTES (STG0_B + 3 * STG_SZ)      // 102912

#define KT_N   32
#define NTILES (S_LEN / KT_N)                      // 32

__global__ __launch_bounds__(256, 2) void attn_mma(
    const __half* __restrict__ Qg, const __half* __restrict__ Kg,
    const __half* __restrict__ Vt, const float* __restrict__ Bias,
    __half* __restrict__ O)
{
    extern __shared__ float sm[];
    char* smc = (char*)sm;
    const uint32_t sb = smem_u32(sm);

    const int q0 = blockIdx.x * 128;
    const int h  = blockIdx.y;
    const int b  = blockIdx.z;
    const int bh = b * NH + h;

    const __half* qp = Qg + (size_t)bh * S_LEN * DK + (size_t)q0 * DK;
    const __half* kp = Kg + (size_t)bh * S_LEN * DK;
    const __half* vtp = Vt + (size_t)bh * DK * S_LEN;
    const float* bp = Bias + (size_t)bh * S_LEN * S_LEN + (size_t)q0 * S_LEN;

    const int tid = threadIdx.x;
    const int wid = tid >> 5, lid = tid & 31;
    const int g = lid >> 2, tg = lid & 3;
    const int qb = wid * 16;
    const int qrow0 = q0 + qb + g;

    // Per-tile async loads into stage st: K 32x64, Vt 64x32, bias 128x32.
#define LOAD_TILE(st, kt)                                                     \
    do {                                                                      \
        const uint32_t stg = sb + STG0_B + (uint32_t)(st) * STG_SZ;           \
        {                                                                     \
            const int row = tid >> 3, off = tid & 7;                          \
            cpasync16(stg + STG_K + row * QPITCH + off * 16,                  \
                      kp + (size_t)((kt) * KT_N + row) * 64 + off * 8);       \
        }                                                                     \
        {                                                                     \
            const int row = tid >> 2, off = tid & 3;                          \
            cpasync16(stg + STG_V + row * VPITCH + off * 16,                  \
                      vtp + (size_t)row * S_LEN + (kt) * KT_N + off * 8);     \
        }                                                                     \
        const float* bpn = bp + (kt) * KT_N;                                  \
        _Pragma("unroll")                                                     \
        for (int i2 = 0; i2 < 4; ++i2) {                                      \
            const int cidx = tid + i2 * 256;                                  \
            const int row = cidx >> 3, off = cidx & 7;                        \
            cpasync16(stg + STG_BI + row * (BPADF * 4) + off * 16,            \
                      bpn + (size_t)row * S_LEN + off * 4);                   \
        }                                                                     \
        cpasync_commit();                                                     \
    } while (0)

    // Prologue: Q tile + tile 0 (group 0), tile 1 (group 1)
#pragma unroll
    for (int i = 0; i < 4; ++i) {
        const int cidx = tid + i * 256;
        const int row = cidx >> 3, off = cidx & 7;
        cpasync16(sb + QS_B + row * QPITCH + off * 16, qp + row * 64 + off * 8);
    }
    LOAD_TILE(0, 0);
    LOAD_TILE(1, 1);

    float l0 = 0.0f, l1 = 0.0f;
    float acc[8][4];
#pragma unroll
    for (int ni = 0; ni < 8; ++ni)
#pragma unroll
        for (int j = 0; j < 4; ++j) acc[ni][j] = 0.0f;

    for (int kt = 0; kt < NTILES; ++kt) {
        if (kt == NTILES - 1) cpasync_wait0(); else cpasync_wait1();
        __syncthreads();   // tile kt resident; prior compute done everywhere

        if (kt + 2 < NTILES) LOAD_TILE((kt + 2) % 3, kt + 2);

        const char* stg = smc + STG0_B + (kt % 3) * STG_SZ;
        const char* Kcur = stg + STG_K;
        const char* Vcur = stg + STG_V;
        const float* Bcur = (const float*)(stg + STG_BI);

        // S = Q @ K^T  (warp: 16 q x 32 k), fp16 m16n8k16
        float s[4][4];
#pragma unroll
        for (int ni = 0; ni < 4; ++ni)
#pragma unroll
            for (int j = 0; j < 4; ++j) s[ni][j] = 0.0f;
#pragma unroll
        for (int kcb = 0; kcb < 4; ++kcb) {
            uint32_t a[4];
            const char* qa = smc + QS_B + (qb + g) * QPITCH + (kcb * 16 + 2 * tg) * 2;
            a[0] = *(const uint32_t*)(qa);
            a[1] = *(const uint32_t*)(qa + 8 * QPITCH);
            a[2] = *(const uint32_t*)(qa + 16);
            a[3] = *(const uint32_t*)(qa + 8 * QPITCH + 16);
#pragma unroll
            for (int ni = 0; ni < 4; ++ni) {
                uint32_t bb[2];
                const char* kb2 = Kcur + (ni * 8 + g) * QPITCH
                                + (kcb * 16 + 2 * tg) * 2;
                bb[0] = *(const uint32_t*)(kb2);
                bb[1] = *(const uint32_t*)(kb2 + 16);
                mma_f16(s[ni], a, bb);
            }
        }

        // mask + bias (staged smem) + exp; pack P to fp16 (A-frag ready)
        uint32_t plo[4], phi[4];
#pragma unroll
        for (int ni = 0; ni < 4; ++ni) {
            const int bco = ni * 8 + tg * 2;
            float2 b0 = *(const float2*)(Bcur + (qb + g) * BPADF + bco);
            float2 b1 = *(const float2*)(Bcur + (qb + g + 8) * BPADF + bco);
            const float p00 = fexp((s[ni][0] == 0.0f ? NEGV : s[ni][0]) + b0.x);
            const float p01 = fexp((s[ni][1] == 0.0f ? NEGV : s[ni][1]) + b0.y);
            const float p10 = fexp((s[ni][2] == 0.0f ? NEGV : s[ni][2]) + b1.x);
            const float p11 = fexp((s[ni][3] == 0.0f ? NEGV : s[ni][3]) + b1.y);
            l0 += p00 + p01;
            l1 += p10 + p11;
            __half2 hlo = __float22half2_rn(make_float2(p00, p01));
            __half2 hhi = __float22half2_rn(make_float2(p10, p11));
            plo[ni] = *(const uint32_t*)&hlo;
            phi[ni] = *(const uint32_t*)&hhi;
        }

        // acc += P @ V : fp16 m16n8k16, 2 k-blocks of 16 keys
#pragma unroll
        for (int j = 0; j < 2; ++j) {
            uint32_t a[4];
            a[0] = plo[2 * j];
            a[1] = phi[2 * j];
            a[2] = plo[2 * j + 1];
            a[3] = phi[2 * j + 1];
#pragma unroll
            for (int ni = 0; ni < 8; ++ni) {
                uint32_t bb[2];
                const char* vb = Vcur + (ni * 8 + g) * VPITCH + (j * 16 + 2 * tg) * 2;
                bb[0] = *(const uint32_t*)(vb);
                bb[1] = *(const uint32_t*)(vb + 16);
                mma_f16(acc[ni], a, bb);
            }
        }
    }

    // Row sums: single quad reduction at the end.
    l0 += __shfl_xor_sync(0xffffffffu, l0, 1);
    l0 += __shfl_xor_sync(0xffffffffu, l0, 2);
    l1 += __shfl_xor_sync(0xffffffffu, l1, 1);
    l1 += __shfl_xor_sync(0xffffffffu, l1, 2);

    // Epilogue: normalize, fp16 (O-proj A operand), store [b][s][hid]
    const float inv0 = 1.0f / l0;
    const float inv1 = 1.0f / l1;
#pragma unroll
    for (int ni = 0; ni < 8; ++ni) {
        const int col = h * DK + ni * 8 + tg * 2;
        __half* o0 = O + (size_t)(b * S_LEN + qrow0) * HID + col;
        __half* o1 = O + (size_t)(b * S_LEN + qrow0 + 8) * HID + col;
        *(__half2*)o0 = __float22half2_rn(
            make_float2(acc[ni][0] * inv0, acc[ni][1] * inv0));
        *(__half2*)o1 = __float22half2_rn(
            make_float2(acc[ni][2] * inv1, acc[ni][3] * inv1));
    }
}

// ---------------------------------------------------------------------------
extern "C" void kernel_launch(void* const* d_in, const int* in_sizes, int n_in,
                              void* d_out, int out_size)
{
    const float* batch = (const float*)d_in[0];
    const float* bias  = (const float*)d_in[1];
    const float* Wq = (const float*)d_in[2];
    const float* bq = (const float*)d_in[3];
    const float* Wk = (const float*)d_in[4];
    const float* bk = (const float*)d_in[5];
    const float* Wv = (const float*)d_in[6];
    const float* bv = (const float*)d_in[7];
    const float* Wo = (const float*)d_in[8];
    const float* bo = (const float*)d_in[9];
    float* out = (float*)d_out;

    __half *qptr, *kptr, *vtptr, *aptr, *xptr, *wqp, *wkp, *wvp, *wop;
    cudaGetSymbolAddress((void**)&qptr, g_q16);
    cudaGetSymbolAddress((void**)&kptr, g_k16);
    cudaGetSymbolAddress((void**)&vtptr, g_vt16);
    cudaGetSymbolAddress((void**)&aptr, g_att16);
    cudaGetSymbolAddress((void**)&xptr, g_x16);
    cudaGetSymbolAddress((void**)&wqp, g_wq16);
    cudaGetSymbolAddress((void**)&wkp, g_wk16);
    cudaGetSymbolAddress((void**)&wvp, g_wv16);
    cudaGetSymbolAddress((void**)&wop, g_wo16);

    static int attr_set = 0;
    if (!attr_set) {
        cudaFuncSetAttribute(gemm_qkv,
                             cudaFuncAttributeMaxDynamicSharedMemorySize,
                             GEMM_SMEM_BYTES);
        cudaFuncSetAttribute(gemm_o,
                             cudaFuncAttributeMaxDynamicSharedMemorySize,
                             GEMM_SMEM_BYTES);
        cudaFuncSetAttribute(attn_mma,
                             cudaFuncAttributeMaxDynamicSharedMemorySize,
                             ATTN_SMEM_BYTES);
        attr_set = 1;
    }

    const int totalG = G8X + 4 * G8W;
    round_all16<<<totalG / 256, 256>>>(
        (const float4*)batch, (const float4*)Wq, (const float4*)Wk,
        (const float4*)Wv, (const float4*)Wo,
        xptr, wqp, wkp, wvp, wop);

    dim3 qkvgrid(24, 32);
    gemm_qkv<<<qkvgrid, 256, GEMM_SMEM_BYTES>>>(xptr, wqp, wkp, wvp,
                                                bq, bk, bv, qptr, kptr, vtptr);

    dim3 agrid(S_LEN / 128, NH, BATCH);
    attn_mma<<<agrid, 256, ATTN_SMEM_BYTES>>>(qptr, kptr, vtptr, bias, aptr);

    dim3 ogrid(HID / 128, M_TOT / 128);
    gemm_o<<<ogrid, 256, GEMM_SMEM_BYTES>>>(aptr, wop, bo, out);
}

// round 16
// speedup vs baseline: 1.2710x; 1.1991x over previous
#include <cuda_runtime.h>
#include <cuda_fp16.h>
#include <cstdint>

// Problem constants
#define S_LEN  1024
#define HID    1024
#define NH     16
#define DK     64
#define BATCH  4
#define M_TOT  (BATCH * S_LEN)     // 4096
#define QK_SCALE 0.125f            // 64^-0.5
#define NEGV   (-9e15f)

// Scratch (static device globals — allocation-free per harness rules)
__device__ __align__(256) __half g_q16 [BATCH * NH * S_LEN * DK];  // [b][h][s][d], pre-scaled
__device__ __align__(256) __half g_k16 [BATCH * NH * S_LEN * DK];  // [b][h][s][d]
__device__ __align__(256) __half g_vt16[BATCH * NH * DK * S_LEN];  // [b][h][d][s]  (V^T)
__device__ __align__(256) __half g_att16[M_TOT * HID];             // attn out
__device__ __align__(256) __half g_x16 [M_TOT * HID];              // fp16 batch
__device__ __align__(256) __half g_wq16[HID * HID];
__device__ __align__(256) __half g_wk16[HID * HID];
__device__ __align__(256) __half g_wv16[HID * HID];
__device__ __align__(256) __half g_wo16[HID * HID];

__device__ __forceinline__ uint32_t smem_u32(const void* p) {
    uint32_t a;
    asm("{ .reg .u64 t; cvta.to.shared.u64 t, %1; cvt.u32.u64 %0, t; }"
        : "=r"(a) : "l"(p));
    return a;
}
__device__ __forceinline__ void cpasync16(uint32_t dst, const void* src) {
    asm volatile("cp.async.ca.shared.global [%0], [%1], 16;"
                 :: "r"(dst), "l"(src) : "memory");
}
__device__ __forceinline__ void cpasync_commit() {
    asm volatile("cp.async.commit_group;" ::: "memory");
}
__device__ __forceinline__ void cpasync_wait0() {
    asm volatile("cp.async.wait_group 0;" ::: "memory");
}
__device__ __forceinline__ void cpasync_wait1() {
    asm volatile("cp.async.wait_group 1;" ::: "memory");
}
__device__ __forceinline__ void ldsm_x4(uint32_t& r0, uint32_t& r1,
                                        uint32_t& r2, uint32_t& r3,
                                        uint32_t addr) {
    asm volatile("ldmatrix.sync.aligned.m8n8.x4.shared.b16 {%0,%1,%2,%3}, [%4];"
                 : "=r"(r0), "=r"(r1), "=r"(r2), "=r"(r3) : "r"(addr));
}

// fp16 MMA, fp32 accumulate: D(16x8) += A(16x16) * B(16x8)
__device__ __forceinline__ void mma_f16(float c[4], const uint32_t a[4],
                                        const uint32_t b[2]) {
    asm volatile(
        "mma.sync.aligned.m16n8k16.row.col.f32.f16.f16.f32 "
        "{%0,%1,%2,%3}, {%4,%5,%6,%7}, {%8,%9}, {%0,%1,%2,%3};"
        : "+f"(c[0]), "+f"(c[1]), "+f"(c[2]), "+f"(c[3])
        : "r"(a[0]), "r"(a[1]), "r"(a[2]), "r"(a[3]),
          "r"(b[0]), "r"(b[1]));
}

// Fast exp on the FMA pipe. Rel err ~4e-5.
__device__ __forceinline__ float fexp(float x) {
    float z = x * 1.44269504f;
    z = fmaxf(z, -125.0f);
    const float C = 12582912.0f;            // 1.5 * 2^23
    float nf = z + C;
    int n = __float_as_int(nf) - 0x4B400000;
    float f = z - (nf - C);
    float p = 0.00961813f;
    p = fmaf(p, f, 0.0555041f);
    p = fmaf(p, f, 0.240227f);
    p = fmaf(p, f, 0.693147f);
    p = fmaf(p, f, 1.0f);
    return __int_as_float(__float_as_int(p) + (n << 23));
}

// ---------------------------------------------------------------------------
// Pre-round pass: batch + 4 weights -> fp16 scratch (single launch).
// ---------------------------------------------------------------------------
#define G8X (M_TOT * HID / 8)   // 524288
#define G8W (HID * HID / 8)     // 131072 = 2^17

__global__ __launch_bounds__(256) void round_all16(
    const float4* __restrict__ x,
    const float4* __restrict__ wq, const float4* __restrict__ wk,
    const float4* __restrict__ wv, const float4* __restrict__ wo,
    __half* __restrict__ ox,
    __half* __restrict__ owq, __half* __restrict__ owk,
    __half* __restrict__ owv, __half* __restrict__ owo)
{
    const int i = blockIdx.x * 256 + threadIdx.x;
    const float4* src;
    __half* dst;
    int off;
    if (i < G8X) {
        src = x; dst = ox; off = i;
    } else {
        const int j = i - G8X;
        const int sel = j >> 17;
        off = j & (G8W - 1);
        src = sel == 0 ? wq : (sel == 1 ? wk : (sel == 2 ? wv : wo));
        dst = sel == 0 ? owq : (sel == 1 ? owk : (sel == 2 ? owv : owo));
    }
    float4 v0 = src[off * 2];
    float4 v1 = src[off * 2 + 1];
    __half2 h[4];
    h[0] = __float22half2_rn(make_float2(v0.x, v0.y));
    h[1] = __float22half2_rn(make_float2(v0.z, v0.w));
    h[2] = __float22half2_rn(make_float2(v1.x, v1.y));
    h[3] = __float22half2_rn(make_float2(v1.z, v1.w));
    *(uint4*)(dst + (size_t)off * 8) = *(const uint4*)h;
}

// ---------------------------------------------------------------------------
// GEMM core: FP16 mma.sync (m16n8k16, fp32 accum), 128x128 tile, BK=64,
// 8 warps, 2-stage cp.async pipeline, ldmatrix fragment loads.
// Rows: 64 fp16 (128 B data), pitch 144 B (conflict-free for ldmatrix).
// ---------------------------------------------------------------------------
#define GPITCH  144
#define ATILE64 (128 * GPITCH)          // 18432 B per operand tile
#define STAGE64 (2 * ATILE64)           // 36864
#define GEMM_SMEM_BYTES (2 * STAGE64)   // 73728

#define LOAD64(s, kk)                                                         \
    do {                                                                      \
        const uint32_t base = sbase + (uint32_t)(s) * STAGE64;                \
        _Pragma("unroll")                                                     \
        for (int t = 0; t < 4; ++t) {                                         \
            const int idx = tid + t * 256;                                    \
            const int row = idx >> 3, off = idx & 7;                          \
            cpasync16(base + row * GPITCH + off * 16,                         \
                      Ap + (size_t)(bm + row) * 1024 + (kk) + off * 8);       \
            cpasync16(base + ATILE64 + row * GPITCH + off * 16,               \
                      Wp + (size_t)(bn + row) * 1024 + (kk) + off * 8);       \
        }                                                                     \
        cpasync_commit();                                                     \
    } while (0)

// Per-lane ldmatrix address offsets (within the A / B tile):
//   aoff: rows (wm*32 + (lid&7) + ((lid>>3)&1)*8), k-offset ((lid>>4)&1)*16B
//   boff: rows (wn*64 + ((lid>>4)&1)*8 + (lid&7)), k-offset ((lid>>3)&1)*16B
#define GEMM_MAINLOOP64()                                                     \
    LOAD64(0, 0);                                                             \
    const uint32_t aoff = (uint32_t)((wm * 32 + (lid & 7) + ((lid >> 3) & 1) * 8) \
                          * GPITCH + ((lid >> 4) & 1) * 16);                  \
    const uint32_t boff = (uint32_t)((wn * 64 + ((lid >> 4) & 1) * 8 + (lid & 7)) \
                          * GPITCH + ((lid >> 3) & 1) * 16);                  \
    for (int i = 0; i < 16; ++i) {                                            \
        cpasync_wait0();                                                      \
        __syncthreads();                                                      \
        if (i + 1 < 16) LOAD64((i + 1) & 1, (i + 1) * 64);                    \
        const uint32_t sA = sbase + (uint32_t)(i & 1) * STAGE64;              \
        const uint32_t sB = sA + ATILE64;                                     \
        _Pragma("unroll")                                                     \
        for (int ks = 0; ks < 4; ++ks) {                                      \
            uint32_t af[2][4];                                                \
            ldsm_x4(af[0][0], af[0][1], af[0][2], af[0][3],                   \
                    sA + aoff + ks * 32);                                     \
            ldsm_x4(af[1][0], af[1][1], af[1][2], af[1][3],                   \
                    sA + aoff + 16 * GPITCH + ks * 32);                       \
            uint32_t bf[8][2];                                                \
            _Pragma("unroll")                                                 \
            for (int a2 = 0; a2 < 4; ++a2) {                                  \
                uint32_t r0, r1, r2, r3;                                      \
                ldsm_x4(r0, r1, r2, r3,                                       \
                        sB + boff + a2 * (16 * GPITCH) + ks * 32);            \
                bf[2 * a2][0] = r0;     bf[2 * a2][1] = r1;                   \
                bf[2 * a2 + 1][0] = r2; bf[2 * a2 + 1][1] = r3;               \
            }                                                                 \
            _Pragma("unroll")                                                 \
            for (int mi = 0; mi < 2; ++mi)                                    \
                _Pragma("unroll")                                             \
                for (int ni = 0; ni < 8; ++ni)                                \
                    mma_f16(c[mi][ni], af[mi], bf[ni]);                       \
        }                                                                     \
    }

// Fused QKV projection: grid (24, 32); bx>>3 selects {Q,K,V}.
__global__ __launch_bounds__(256, 2) void gemm_qkv(
    const __half* __restrict__ A,
    const __half* __restrict__ Wqp, const __half* __restrict__ Wkp,
    const __half* __restrict__ Wvp,
    const float* __restrict__ bq, const float* __restrict__ bk,
    const float* __restrict__ bv,
    __half* __restrict__ oq, __half* __restrict__ ok, __half* __restrict__ ovt)
{
    extern __shared__ float sm[];
    const uint32_t sbase = smem_u32(sm);

    const int tid = threadIdx.x;
    const int wid = tid >> 5, lid = tid & 31;
    const int which = blockIdx.x >> 3;
    const int bn = (blockIdx.x & 7) * 128;
    const int bm = blockIdx.y * 128;
    const int wm = wid >> 1, wn = wid & 1;
    const int g = lid >> 2, tg = lid & 3;

    const __half* Wp  = which == 0 ? Wqp : (which == 1 ? Wkp : Wvp);
    const float* bias = which == 0 ? bq  : (which == 1 ? bk  : bv);
    const __half* Ap = A;

    float c[2][8][4];
#pragma unroll
    for (int mi = 0; mi < 2; ++mi)
#pragma unroll
        for (int ni = 0; ni < 8; ++ni)
#pragma unroll
            for (int k = 0; k < 4; ++k) c[mi][ni][k] = 0.0f;

    GEMM_MAINLOOP64();

    if (which < 2) {
        __half* out = which == 0 ? oq : ok;
        const float scale = which == 0 ? QK_SCALE : 1.0f;
#pragma unroll
        for (int mi = 0; mi < 2; ++mi) {
            const int rowa = bm + wm * 32 + mi * 16 + g;
            const int rowb = rowa + 8;
#pragma unroll
            for (int ni = 0; ni < 8; ++ni) {
                const int col = bn + wn * 64 + ni * 8 + tg * 2;
                const float b0 = bias[col], b1 = bias[col + 1];
                __half2 h0 = __float22half2_rn(
                    make_float2((c[mi][ni][0] + b0) * scale,
                                (c[mi][ni][1] + b1) * scale));
                __half2 h1 = __float22half2_rn(
                    make_float2((c[mi][ni][2] + b0) * scale,
                                (c[mi][ni][3] + b1) * scale));
                const int h = col >> 6, d = col & 63;
                const int ba = rowa >> 10, sa = rowa & 1023;
                const int bb = rowb >> 10, sb2 = rowb & 1023;
                *(__half2*)(out + (((size_t)(ba * NH + h) * S_LEN + sa) * DK + d)) = h0;
                *(__half2*)(out + (((size_t)(bb * NH + h) * S_LEN + sb2) * DK + d)) = h1;
            }
        }
    } else {
        // V: stage transposed [n][m] fp16 tile (pitch 136 halfs)
        __syncthreads();
        __half* st = (__half*)sm;
#pragma unroll
        for (int mi = 0; mi < 2; ++mi) {
            const int ma = wm * 32 + mi * 16 + g;
            const int mb = ma + 8;
#pragma unroll
            for (int ni = 0; ni < 8; ++ni) {
                const int nl = wn * 64 + ni * 8 + tg * 2;
                const float b0 = bias[bn + nl], b1 = bias[bn + nl + 1];
                st[(nl + 0) * 136 + ma] = __float2half_rn(c[mi][ni][0] + b0);
                st[(nl + 1) * 136 + ma] = __float2half_rn(c[mi][ni][1] + b1);
                st[(nl + 0) * 136 + mb] = __float2half_rn(c[mi][ni][2] + b0);
                st[(nl + 1) * 136 + mb] = __float2half_rn(c[mi][ni][3] + b1);
            }
        }
        __syncthreads();
        const int r = tid >> 1, sel = tid & 1;
        const int col = bn + r;
        const int hh = col >> 6, d = col & 63;
        const int bb2 = bm >> 10;
        const int s0 = (bm & 1023) + sel * 64;
        __half* dst = ovt + (((size_t)(bb2 * NH + hh) * DK + d) * S_LEN + s0);
        const __half* srcp = st + r * 136 + sel * 64;
#pragma unroll
        for (int k2 = 0; k2 < 8; ++k2)
            *(uint4*)(dst + k2 * 8) = *(const uint4*)(srcp + k2 * 8);
    }
}

// Output projection: fp16 inputs, row-major fp32 out.
__global__ __launch_bounds__(256, 2) void gemm_o(
    const __half* __restrict__ A, const __half* __restrict__ W,
    const float* __restrict__ bias, float* __restrict__ out)
{
    extern __shared__ float sm[];
    const uint32_t sbase = smem_u32(sm);

    const int tid = threadIdx.x;
    const int wid = tid >> 5, lid = tid & 31;
    const int bn = blockIdx.x * 128;
    const int bm = blockIdx.y * 128;
    const int wm = wid >> 1, wn = wid & 1;
    const int g = lid >> 2, tg = lid & 3;
    const __half* Ap = A;
    const __half* Wp = W;

    float c[2][8][4];
#pragma unroll
    for (int mi = 0; mi < 2; ++mi)
#pragma unroll
        for (int ni = 0; ni < 8; ++ni)
#pragma unroll
            for (int k = 0; k < 4; ++k) c[mi][ni][k] = 0.0f;

    GEMM_MAINLOOP64();

#pragma unroll
    for (int mi = 0; mi < 2; ++mi) {
        const int rowa = bm + wm * 32 + mi * 16 + g;
        const int rowb = rowa + 8;
#pragma unroll
        for (int ni = 0; ni < 8; ++ni) {
            const int col = bn + wn * 64 + ni * 8 + tg * 2;
            const float b0 = bias[col], b1 = bias[col + 1];
            *(float2*)(out + (size_t)rowa * HID + col) =
                make_float2(c[mi][ni][0] + b0, c[mi][ni][1] + b1);
            *(float2*)(out + (size_t)rowb * HID + col) =
                make_float2(c[mi][ni][2] + b0, c[mi][ni][3] + b1);
        }
    }
}

// ---------------------------------------------------------------------------
// FP16 tensor-core flash attention (exact R15). K-tiles of 32. Fixed-zero-max
// softmax. 3-stage cp.async ring on K/V/bias, two-tile lookahead.
// ---------------------------------------------------------------------------
#define QPITCH 144
#define VPITCH 80
#define BPADF  36
#define QS_B   0
#define STG_K  0
#define STG_V  (32 * QPITCH)                       // 4608
#define STG_BI (STG_V + 64 * VPITCH)               // 9728
#define STG_SZ (STG_BI + 128 * BPADF * 4)          // 28160
#define STG0_B (128 * QPITCH)                      // 18432 (after Q)
#define ATTN_SMEM_BYTES (STG0_B + 3 * STG_SZ)      // 102912

#define KT_N   32
#define NTILES (S_LEN / KT_N)                      // 32

__global__ __launch_bounds__(256, 2) void attn_mma(
    const __half* __restrict__ Qg, const __half* __restrict__ Kg,
    const __half* __restrict__ Vt, const float* __restrict__ Bias,
    __half* __restrict__ O)
{
    extern __shared__ float sm[];
    char* smc = (char*)sm;
    const uint32_t sb = smem_u32(sm);

    const int q0 = blockIdx.x * 128;
    const int h  = blockIdx.y;
    const int b  = blockIdx.z;
    const int bh = b * NH + h;

    const __half* qp = Qg + (size_t)bh * S_LEN * DK + (size_t)q0 * DK;
    const __half* kp = Kg + (size_t)bh * S_LEN * DK;
    const __half* vtp = Vt + (size_t)bh * DK * S_LEN;
    const float* bp = Bias + (size_t)bh * S_LEN * S_LEN + (size_t)q0 * S_LEN;

    const int tid = threadIdx.x;
    const int wid = tid >> 5, lid = tid & 31;
    const int g = lid >> 2, tg = lid & 3;
    const int qb = wid * 16;
    const int qrow0 = q0 + qb + g;

#define LOAD_TILE(st, kt)                                                     \
    do {                                                                      \
        const uint32_t stg = sb + STG0_B + (uint32_t)(st) * STG_SZ;           \
        {                                                                     \
            const int row = tid >> 3, off = tid & 7;                          \
            cpasync16(stg + STG_K + row * QPITCH + off * 16,                  \
                      kp + (size_t)((kt) * KT_N + row) * 64 + off * 8);       \
        }                                                                     \
        {                                                                     \
            const int row = tid >> 2, off = tid & 3;                          \
            cpasync16(stg + STG_V + row * VPITCH + off * 16,                  \
                      vtp + (size_t)row * S_LEN + (kt) * KT_N + off * 8);     \
        }                                                                     \
        const float* bpn = bp + (kt) * KT_N;                                  \
        _Pragma("unroll")                                                     \
        for (int i2 = 0; i2 < 4; ++i2) {                                      \
            const int cidx = tid + i2 * 256;                                  \
            const int row = cidx >> 3, off = cidx & 7;                        \
            cpasync16(stg + STG_BI + row * (BPADF * 4) + off * 16,            \
                      bpn + (size_t)row * S_LEN + off * 4);                   \
        }                                                                     \
        cpasync_commit();                                                     \
    } while (0)

#pragma unroll
    for (int i = 0; i < 4; ++i) {
        const int cidx = tid + i * 256;
        const int row = cidx >> 3, off = cidx & 7;
        cpasync16(sb + QS_B + row * QPITCH + off * 16, qp + row * 64 + off * 8);
    }
    LOAD_TILE(0, 0);
    LOAD_TILE(1, 1);

    float l0 = 0.0f, l1 = 0.0f;
    float acc[8][4];
#pragma unroll
    for (int ni = 0; ni < 8; ++ni)
#pragma unroll
        for (int j = 0; j < 4; ++j) acc[ni][j] = 0.0f;

    for (int kt = 0; kt < NTILES; ++kt) {
        if (kt == NTILES - 1) cpasync_wait0(); else cpasync_wait1();
        __syncthreads();

        if (kt + 2 < NTILES) LOAD_TILE((kt + 2) % 3, kt + 2);

        const char* stg = smc + STG0_B + (kt % 3) * STG_SZ;
        const char* Kcur = stg + STG_K;
        const char* Vcur = stg + STG_V;
        const float* Bcur = (const float*)(stg + STG_BI);

        float s[4][4];
#pragma unroll
        for (int ni = 0; ni < 4; ++ni)
#pragma unroll
            for (int j = 0; j < 4; ++j) s[ni][j] = 0.0f;
#pragma unroll
        for (int kcb = 0; kcb < 4; ++kcb) {
            uint32_t a[4];
            const char* qa = smc + QS_B + (qb + g) * QPITCH + (kcb * 16 + 2 * tg) * 2;
            a[0] = *(const uint32_t*)(qa);
            a[1] = *(const uint32_t*)(qa + 8 * QPITCH);
            a[2] = *(const uint32_t*)(qa + 16);
            a[3] = *(const uint32_t*)(qa + 8 * QPITCH + 16);
#pragma unroll
            for (int ni = 0; ni < 4; ++ni) {
                uint32_t bb[2];
                const char* kb2 = Kcur + (ni * 8 + g) * QPITCH
                                + (kcb * 16 + 2 * tg) * 2;
                bb[0] = *(const uint32_t*)(kb2);
                bb[1] = *(const uint32_t*)(kb2 + 16);
                mma_f16(s[ni], a, bb);
            }
        }

        uint32_t plo[4], phi[4];
#pragma unroll
        for (int ni = 0; ni < 4; ++ni) {
            const int bco = ni * 8 + tg * 2;
            float2 b0 = *(const float2*)(Bcur + (qb + g) * BPADF + bco);
            float2 b1 = *(const float2*)(Bcur + (qb + g + 8) * BPADF + bco);
            const float p00 = fexp((s[ni][0] == 0.0f ? NEGV : s[ni][0]) + b0.x);
            const float p01 = fexp((s[ni][1] == 0.0f ? NEGV : s[ni][1]) + b0.y);
            const float p10 = fexp((s[ni][2] == 0.0f ? NEGV : s[ni][2]) + b1.x);
            const float p11 = fexp((s[ni][3] == 0.0f ? NEGV : s[ni][3]) + b1.y);
            l0 += p00 + p01;
            l1 += p10 + p11;
            __half2 hlo = __float22half2_rn(make_float2(p00, p01));
            __half2 hhi = __float22half2_rn(make_float2(p10, p11));
            plo[ni] = *(const uint32_t*)&hlo;
            phi[ni] = *(const uint32_t*)&hhi;
        }

#pragma unroll
        for (int j = 0; j < 2; ++j) {
            uint32_t a[4];
            a[0] = plo[2 * j];
            a[1] = phi[2 * j];
            a[2] = plo[2 * j + 1];
            a[3] = phi[2 * j + 1];
#pragma unroll
            for (int ni = 0; ni < 8; ++ni) {
                uint32_t bb[2];
                const char* vb = Vcur + (ni * 8 + g) * VPITCH + (j * 16 + 2 * tg) * 2;
                bb[0] = *(const uint32_t*)(vb);
                bb[1] = *(const uint32_t*)(vb + 16);
                mma_f16(acc[ni], a, bb);
            }
        }
    }

    l0 += __shfl_xor_sync(0xffffffffu, l0, 1);
    l0 += __shfl_xor_sync(0xffffffffu, l0, 2);
    l1 += __shfl_xor_sync(0xffffffffu, l1, 1);
    l1 += __shfl_xor_sync(0xffffffffu, l1, 2);

    const float inv0 = 1.0f / l0;
    const float inv1 = 1.0f / l1;
#pragma unroll
    for (int ni = 0; ni < 8; ++ni) {
        const int col = h * DK + ni * 8 + tg * 2;
        __half* o0 = O + (size_t)(b * S_LEN + qrow0) * HID + col;
        __half* o1 = O + (size_t)(b * S_LEN + qrow0 + 8) * HID + col;
        *(__half2*)o0 = __float22half2_rn(
            make_float2(acc[ni][0] * inv0, acc[ni][1] * inv0));
        *(__half2*)o1 = __float22half2_rn(
            make_float2(acc[ni][2] * inv1, acc[ni][3] * inv1));
    }
}

// ---------------------------------------------------------------------------
extern "C" void kernel_launch(void* const* d_in, const int* in_sizes, int n_in,
                              void* d_out, int out_size)
{
    const float* batch = (const float*)d_in[0];
    const float* bias  = (const float*)d_in[1];
    const float* Wq = (const float*)d_in[2];
    const float* bq = (const float*)d_in[3];
    const float* Wk = (const float*)d_in[4];
    const float* bk = (const float*)d_in[5];
    const float* Wv = (const float*)d_in[6];
    const float* bv = (const float*)d_in[7];
    const float* Wo = (const float*)d_in[8];
    const float* bo = (const float*)d_in[9];
    float* out = (float*)d_out;

    __half *qptr, *kptr, *vtptr, *aptr, *xptr, *wqp, *wkp, *wvp, *wop;
    cudaGetSymbolAddress((void**)&qptr, g_q16);
    cudaGetSymbolAddress((void**)&kptr, g_k16);
    cudaGetSymbolAddress((void**)&vtptr, g_vt16);
    cudaGetSymbolAddress((void**)&aptr, g_att16);
    cudaGetSymbolAddress((void**)&xptr, g_x16);
    cudaGetSymbolAddress((void**)&wqp, g_wq16);
    cudaGetSymbolAddress((void**)&wkp, g_wk16);
    cudaGetSymbolAddress((void**)&wvp, g_wv16);
    cudaGetSymbolAddress((void**)&wop, g_wo16);

    static int attr_set = 0;
    if (!attr_set) {
        cudaFuncSetAttribute(gemm_qkv,
                             cudaFuncAttributeMaxDynamicSharedMemorySize,
                             GEMM_SMEM_BYTES);
        cudaFuncSetAttribute(gemm_o,
                             cudaFuncAttributeMaxDynamicSharedMemorySize,
                             GEMM_SMEM_BYTES);
        cudaFuncSetAttribute(attn_mma,
                             cudaFuncAttributeMaxDynamicSharedMemorySize,
                             ATTN_SMEM_BYTES);
        attr_set = 1;
    }

    const int totalG = G8X + 4 * G8W;
    round_all16<<<totalG / 256, 256>>>(
        (const float4*)batch, (const float4*)Wq, (const float4*)Wk,
        (const float4*)Wv, (const float4*)Wo,
        xptr, wqp, wkp, wvp, wop);

    dim3 qkvgrid(24, 32);
    gemm_qkv<<<qkvgrid, 256, GEMM_SMEM_BYTES>>>(xptr, wqp, wkp, wvp,
                                                bq, bk, bv, qptr, kptr, vtptr);

    dim3 agrid(S_LEN / 128, NH, BATCH);
    attn_mma<<<agrid, 256, ATTN_SMEM_BYTES>>>(qptr, kptr, vtptr, bias, aptr);

    dim3 ogrid(HID / 128, M_TOT / 128);
    gemm_o<<<ogrid, 256, GEMM_SMEM_BYTES>>>(aptr, wop, bo, out);
}

// round 17
// speedup vs baseline: 1.3337x; 1.0493x over previous
#include <cuda_runtime.h>
#include <cuda_fp16.h>
#include <cstdint>

// Problem constants
#define S_LEN  1024
#define HID    1024
#define NH     16
#define DK     64
#define BATCH  4
#define M_TOT  (BATCH * S_LEN)     // 4096
#define QK_SCALE 0.125f            // 64^-0.5
#define NEGV   (-9e15f)

// Scratch (static device globals — allocation-free per harness rules)
__device__ __align__(256) __half g_q16 [BATCH * NH * S_LEN * DK];  // [b][h][s][d], pre-scaled
__device__ __align__(256) __half g_k16 [BATCH * NH * S_LEN * DK];  // [b][h][s][d]
__device__ __align__(256) __half g_vt16[BATCH * NH * DK * S_LEN];  // [b][h][d][s]  (V^T)
__device__ __align__(256) __half g_att16[M_TOT * HID];             // attn out
__device__ __align__(256) __half g_x16 [M_TOT * HID];              // fp16 batch
__device__ __align__(256) __half g_wq16[HID * HID];
__device__ __align__(256) __half g_wk16[HID * HID];
__device__ __align__(256) __half g_wv16[HID * HID];
__device__ __align__(256) __half g_wo16[HID * HID];

__device__ __forceinline__ uint32_t smem_u32(const void* p) {
    uint32_t a;
    asm("{ .reg .u64 t; cvta.to.shared.u64 t, %1; cvt.u32.u64 %0, t; }"
        : "=r"(a) : "l"(p));
    return a;
}
__device__ __forceinline__ void cpasync16(uint32_t dst, const void* src) {
    asm volatile("cp.async.ca.shared.global [%0], [%1], 16;"
                 :: "r"(dst), "l"(src) : "memory");
}
__device__ __forceinline__ void cpasync_commit() {
    asm volatile("cp.async.commit_group;" ::: "memory");
}
__device__ __forceinline__ void cpasync_wait0() {
    asm volatile("cp.async.wait_group 0;" ::: "memory");
}
__device__ __forceinline__ void cpasync_wait1() {
    asm volatile("cp.async.wait_group 1;" ::: "memory");
}
__device__ __forceinline__ void ldsm_x4(uint32_t& r0, uint32_t& r1,
                                        uint32_t& r2, uint32_t& r3,
                                        uint32_t addr) {
    asm volatile("ldmatrix.sync.aligned.m8n8.x4.shared.b16 {%0,%1,%2,%3}, [%4];"
                 : "=r"(r0), "=r"(r1), "=r"(r2), "=r"(r3) : "r"(addr));
}

// fp16 MMA, fp32 accumulate: D(16x8) += A(16x16) * B(16x8)
__device__ __forceinline__ void mma_f16(float c[4], const uint32_t a[4],
                                        const uint32_t b[2]) {
    asm volatile(
        "mma.sync.aligned.m16n8k16.row.col.f32.f16.f16.f32 "
        "{%0,%1,%2,%3}, {%4,%5,%6,%7}, {%8,%9}, {%0,%1,%2,%3};"
        : "+f"(c[0]), "+f"(c[1]), "+f"(c[2]), "+f"(c[3])
        : "r"(a[0]), "r"(a[1]), "r"(a[2]), "r"(a[3]),
          "r"(b[0]), "r"(b[1]));
}

// Fast exp on the FMA pipe. Rel err ~4e-5.
__device__ __forceinline__ float fexp(float x) {
    float z = x * 1.44269504f;
    z = fmaxf(z, -125.0f);
    const float C = 12582912.0f;            // 1.5 * 2^23
    float nf = z + C;
    int n = __float_as_int(nf) - 0x4B400000;
    float f = z - (nf - C);
    float p = 0.00961813f;
    p = fmaf(p, f, 0.0555041f);
    p = fmaf(p, f, 0.240227f);
    p = fmaf(p, f, 0.693147f);
    p = fmaf(p, f, 1.0f);
    return __int_as_float(__float_as_int(p) + (n << 23));
}

// ---------------------------------------------------------------------------
// Pre-round pass: batch + 4 weights -> fp16 scratch (single launch).
// ---------------------------------------------------------------------------
#define G8X (M_TOT * HID / 8)   // 524288
#define G8W (HID * HID / 8)     // 131072 = 2^17

__global__ __launch_bounds__(256) void round_all16(
    const float4* __restrict__ x,
    const float4* __restrict__ wq, const float4* __restrict__ wk,
    const float4* __restrict__ wv, const float4* __restrict__ wo,
    __half* __restrict__ ox,
    __half* __restrict__ owq, __half* __restrict__ owk,
    __half* __restrict__ owv, __half* __restrict__ owo)
{
    const int i = blockIdx.x * 256 + threadIdx.x;
    const float4* src;
    __half* dst;
    int off;
    if (i < G8X) {
        src = x; dst = ox; off = i;
    } else {
        const int j = i - G8X;
        const int sel = j >> 17;
        off = j & (G8W - 1);
        src = sel == 0 ? wq : (sel == 1 ? wk : (sel == 2 ? wv : wo));
        dst = sel == 0 ? owq : (sel == 1 ? owk : (sel == 2 ? owv : owo));
    }
    float4 v0 = src[off * 2];
    float4 v1 = src[off * 2 + 1];
    __half2 h[4];
    h[0] = __float22half2_rn(make_float2(v0.x, v0.y));
    h[1] = __float22half2_rn(make_float2(v0.z, v0.w));
    h[2] = __float22half2_rn(make_float2(v1.x, v1.y));
    h[3] = __float22half2_rn(make_float2(v1.z, v1.w));
    *(uint4*)(dst + (size_t)off * 8) = *(const uint4*)h;
}

// ---------------------------------------------------------------------------
// GEMM core: FP16 mma.sync (m16n8k16, fp32 accum), 128x128 tile, BK=64,
// 8 warps, 2-stage cp.async pipeline, ldmatrix fragment loads. (R16)
// ---------------------------------------------------------------------------
#define GPITCH  144
#define ATILE64 (128 * GPITCH)          // 18432 B per operand tile
#define STAGE64 (2 * ATILE64)           // 36864
#define GEMM_SMEM_BYTES (2 * STAGE64)   // 73728

#define LOAD64(s, kk)                                                         \
    do {                                                                      \
        const uint32_t base = sbase + (uint32_t)(s) * STAGE64;                \
        _Pragma("unroll")                                                     \
        for (int t = 0; t < 4; ++t) {                                         \
            const int idx = tid + t * 256;                                    \
            const int row = idx >> 3, off = idx & 7;                          \
            cpasync16(base + row * GPITCH + off * 16,                         \
                      Ap + (size_t)(bm + row) * 1024 + (kk) + off * 8);       \
            cpasync16(base + ATILE64 + row * GPITCH + off * 16,               \
                      Wp + (size_t)(bn + row) * 1024 + (kk) + off * 8);       \
        }                                                                     \
        cpasync_commit();                                                     \
    } while (0)

#define GEMM_MAINLOOP64()                                                     \
    LOAD64(0, 0);                                                             \
    const uint32_t aoff = (uint32_t)((wm * 32 + (lid & 7) + ((lid >> 3) & 1) * 8) \
                          * GPITCH + ((lid >> 4) & 1) * 16);                  \
    const uint32_t boff = (uint32_t)((wn * 64 + ((lid >> 4) & 1) * 8 + (lid & 7)) \
                          * GPITCH + ((lid >> 3) & 1) * 16);                  \
    for (int i = 0; i < 16; ++i) {                                            \
        cpasync_wait0();                                                      \
        __syncthreads();                                                      \
        if (i + 1 < 16) LOAD64((i + 1) & 1, (i + 1) * 64);                    \
        const uint32_t sA = sbase + (uint32_t)(i & 1) * STAGE64;              \
        const uint32_t sB = sA + ATILE64;                                     \
        _Pragma("unroll")                                                     \
        for (int ks = 0; ks < 4; ++ks) {                                      \
            uint32_t af[2][4];                                                \
            ldsm_x4(af[0][0], af[0][1], af[0][2], af[0][3],                   \
                    sA + aoff + ks * 32);                                     \
            ldsm_x4(af[1][0], af[1][1], af[1][2], af[1][3],                   \
                    sA + aoff + 16 * GPITCH + ks * 32);                       \
            uint32_t bf[8][2];                                                \
            _Pragma("unroll")                                                 \
            for (int a2 = 0; a2 < 4; ++a2) {                                  \
                uint32_t r0, r1, r2, r3;                                      \
                ldsm_x4(r0, r1, r2, r3,                                       \
                        sB + boff + a2 * (16 * GPITCH) + ks * 32);            \
                bf[2 * a2][0] = r0;     bf[2 * a2][1] = r1;                   \
                bf[2 * a2 + 1][0] = r2; bf[2 * a2 + 1][1] = r3;               \
            }                                                                 \
            _Pragma("unroll")                                                 \
            for (int mi = 0; mi < 2; ++mi)                                    \
                _Pragma("unroll")                                             \
                for (int ni = 0; ni < 8; ++ni)                                \
                    mma_f16(c[mi][ni], af[mi], bf[ni]);                       \
        }                                                                     \
    }

// Fused QKV projection: grid (24, 32); bx>>3 selects {Q,K,V}.
__global__ __launch_bounds__(256, 2) void gemm_qkv(
    const __half* __restrict__ A,
    const __half* __restrict__ Wqp, const __half* __restrict__ Wkp,
    const __half* __restrict__ Wvp,
    const float* __restrict__ bq, const float* __restrict__ bk,
    const float* __restrict__ bv,
    __half* __restrict__ oq, __half* __restrict__ ok, __half* __restrict__ ovt)
{
    extern __shared__ float sm[];
    const uint32_t sbase = smem_u32(sm);

    const int tid = threadIdx.x;
    const int wid = tid >> 5, lid = tid & 31;
    const int which = blockIdx.x >> 3;
    const int bn = (blockIdx.x & 7) * 128;
    const int bm = blockIdx.y * 128;
    const int wm = wid >> 1, wn = wid & 1;
    const int g = lid >> 2, tg = lid & 3;

    const __half* Wp  = which == 0 ? Wqp : (which == 1 ? Wkp : Wvp);
    const float* bias = which == 0 ? bq  : (which == 1 ? bk  : bv);
    const __half* Ap = A;

    float c[2][8][4];
#pragma unroll
    for (int mi = 0; mi < 2; ++mi)
#pragma unroll
        for (int ni = 0; ni < 8; ++ni)
#pragma unroll
            for (int k = 0; k < 4; ++k) c[mi][ni][k] = 0.0f;

    GEMM_MAINLOOP64();

    if (which < 2) {
        __half* out = which == 0 ? oq : ok;
        const float scale = which == 0 ? QK_SCALE : 1.0f;
#pragma unroll
        for (int mi = 0; mi < 2; ++mi) {
            const int rowa = bm + wm * 32 + mi * 16 + g;
            const int rowb = rowa + 8;
#pragma unroll
            for (int ni = 0; ni < 8; ++ni) {
                const int col = bn + wn * 64 + ni * 8 + tg * 2;
                const float b0 = bias[col], b1 = bias[col + 1];
                __half2 h0 = __float22half2_rn(
                    make_float2((c[mi][ni][0] + b0) * scale,
                                (c[mi][ni][1] + b1) * scale));
                __half2 h1 = __float22half2_rn(
                    make_float2((c[mi][ni][2] + b0) * scale,
                                (c[mi][ni][3] + b1) * scale));
                const int h = col >> 6, d = col & 63;
                const int ba = rowa >> 10, sa = rowa & 1023;
                const int bb = rowb >> 10, sb2 = rowb & 1023;
                *(__half2*)(out + (((size_t)(ba * NH + h) * S_LEN + sa) * DK + d)) = h0;
                *(__half2*)(out + (((size_t)(bb * NH + h) * S_LEN + sb2) * DK + d)) = h1;
            }
        }
    } else {
        // V: stage transposed [n][m] fp16 tile (pitch 136 halfs)
        __syncthreads();
        __half* st = (__half*)sm;
#pragma unroll
        for (int mi = 0; mi < 2; ++mi) {
            const int ma = wm * 32 + mi * 16 + g;
            const int mb = ma + 8;
#pragma unroll
            for (int ni = 0; ni < 8; ++ni) {
                const int nl = wn * 64 + ni * 8 + tg * 2;
                const float b0 = bias[bn + nl], b1 = bias[bn + nl + 1];
                st[(nl + 0) * 136 + ma] = __float2half_rn(c[mi][ni][0] + b0);
                st[(nl + 1) * 136 + ma] = __float2half_rn(c[mi][ni][1] + b1);
                st[(nl + 0) * 136 + mb] = __float2half_rn(c[mi][ni][2] + b0);
                st[(nl + 1) * 136 + mb] = __float2half_rn(c[mi][ni][3] + b1);
            }
        }
        __syncthreads();
        const int r = tid >> 1, sel = tid & 1;
        const int col = bn + r;
        const int hh = col >> 6, d = col & 63;
        const int bb2 = bm >> 10;
        const int s0 = (bm & 1023) + sel * 64;
        __half* dst = ovt + (((size_t)(bb2 * NH + hh) * DK + d) * S_LEN + s0);
        const __half* srcp = st + r * 136 + sel * 64;
#pragma unroll
        for (int k2 = 0; k2 < 8; ++k2)
            *(uint4*)(dst + k2 * 8) = *(const uint4*)(srcp + k2 * 8);
    }
}

// Output projection: fp16 inputs, row-major fp32 out.
__global__ __launch_bounds__(256, 2) void gemm_o(
    const __half* __restrict__ A, const __half* __restrict__ W,
    const float* __restrict__ bias, float* __restrict__ out)
{
    extern __shared__ float sm[];
    const uint32_t sbase = smem_u32(sm);

    const int tid = threadIdx.x;
    const int wid = tid >> 5, lid = tid & 31;
    const int bn = blockIdx.x * 128;
    const int bm = blockIdx.y * 128;
    const int wm = wid >> 1, wn = wid & 1;
    const int g = lid >> 2, tg = lid & 3;
    const __half* Ap = A;
    const __half* Wp = W;

    float c[2][8][4];
#pragma unroll
    for (int mi = 0; mi < 2; ++mi)
#pragma unroll
        for (int ni = 0; ni < 8; ++ni)
#pragma unroll
            for (int k = 0; k < 4; ++k) c[mi][ni][k] = 0.0f;

    GEMM_MAINLOOP64();

#pragma unroll
    for (int mi = 0; mi < 2; ++mi) {
        const int rowa = bm + wm * 32 + mi * 16 + g;
        const int rowb = rowa + 8;
#pragma unroll
        for (int ni = 0; ni < 8; ++ni) {
            const int col = bn + wn * 64 + ni * 8 + tg * 2;
            const float b0 = bias[col], b1 = bias[col + 1];
            *(float2*)(out + (size_t)rowa * HID + col) =
                make_float2(c[mi][ni][0] + b0, c[mi][ni][1] + b1);
            *(float2*)(out + (size_t)rowb * HID + col) =
                make_float2(c[mi][ni][2] + b0, c[mi][ni][3] + b1);
        }
    }
}

// ---------------------------------------------------------------------------
// FP16 tensor-core flash attention. K-tiles of 32. Fixed-zero-max softmax.
// 3-stage cp.async ring on K/V/bias (two-tile lookahead) + ldmatrix
// fragment loads for Q, K and V^T (GEMM-verified lane mappings).
// ---------------------------------------------------------------------------
#define QPITCH 144
#define VPITCH 80
#define BPADF  36
#define QS_B   0
#define STG_K  0
#define STG_V  (32 * QPITCH)                       // 4608
#define STG_BI (STG_V + 64 * VPITCH)               // 9728
#define STG_SZ (STG_BI + 128 * BPADF * 4)          // 28160
#define STG0_B (128 * QPITCH)                      // 18432 (after Q)
#define ATTN_SMEM_BYTES (STG0_B + 3 * STG_SZ)      // 102912

#define KT_N   32
#define NTILES (S_LEN / KT_N)                      // 32

__global__ __launch_bounds__(256, 2) void attn_mma(
    const __half* __restrict__ Qg, const __half* __restrict__ Kg,
    const __half* __restrict__ Vt, const float* __restrict__ Bias,
    __half* __restrict__ O)
{
    extern __shared__ float sm[];
    char* smc = (char*)sm;
    const uint32_t sb = smem_u32(sm);

    const int q0 = blockIdx.x * 128;
    const int h  = blockIdx.y;
    const int b  = blockIdx.z;
    const int bh = b * NH + h;

    const __half* qp = Qg + (size_t)bh * S_LEN * DK + (size_t)q0 * DK;
    const __half* kp = Kg + (size_t)bh * S_LEN * DK;
    const __half* vtp = Vt + (size_t)bh * DK * S_LEN;
    const float* bp = Bias + (size_t)bh * S_LEN * S_LEN + (size_t)q0 * S_LEN;

    const int tid = threadIdx.x;
    const int wid = tid >> 5, lid = tid & 31;
    const int g = lid >> 2, tg = lid & 3;
    const int qb = wid * 16;
    const int qrow0 = q0 + qb + g;

    // ldmatrix lane-address offsets (GEMM-verified patterns)
    const uint32_t aoffQ = (uint32_t)((qb + (lid & 7) + ((lid >> 3) & 1) * 8)
                           * QPITCH + ((lid >> 4) & 1) * 16);
    const uint32_t boffK = (uint32_t)((((lid >> 4) & 1) * 8 + (lid & 7))
                           * QPITCH + ((lid >> 3) & 1) * 16);
    const uint32_t boffV = (uint32_t)((((lid >> 4) & 1) * 8 + (lid & 7))
                           * VPITCH + ((lid >> 3) & 1) * 16);

#define LOAD_TILE(st, kt)                                                     \
    do {                                                                      \
        const uint32_t stg = sb + STG0_B + (uint32_t)(st) * STG_SZ;           \
        {                                                                     \
            const int row = tid >> 3, off = tid & 7;                          \
            cpasync16(stg + STG_K + row * QPITCH + off * 16,                  \
                      kp + (size_t)((kt) * KT_N + row) * 64 + off * 8);       \
        }                                                                     \
        {                                                                     \
            const int row = tid >> 2, off = tid & 3;                          \
            cpasync16(stg + STG_V + row * VPITCH + off * 16,                  \
                      vtp + (size_t)row * S_LEN + (kt) * KT_N + off * 8);     \
        }                                                                     \
        const float* bpn = bp + (kt) * KT_N;                                  \
        _Pragma("unroll")                                                     \
        for (int i2 = 0; i2 < 4; ++i2) {                                      \
            const int cidx = tid + i2 * 256;                                  \
            const int row = cidx >> 3, off = cidx & 7;                        \
            cpasync16(stg + STG_BI + row * (BPADF * 4) + off * 16,            \
                      bpn + (size_t)row * S_LEN + off * 4);                   \
        }                                                                     \
        cpasync_commit();                                                     \
    } while (0)

#pragma unroll
    for (int i = 0; i < 4; ++i) {
        const int cidx = tid + i * 256;
        const int row = cidx >> 3, off = cidx & 7;
        cpasync16(sb + QS_B + row * QPITCH + off * 16, qp + row * 64 + off * 8);
    }
    LOAD_TILE(0, 0);
    LOAD_TILE(1, 1);

    float l0 = 0.0f, l1 = 0.0f;
    float acc[8][4];
#pragma unroll
    for (int ni = 0; ni < 8; ++ni)
#pragma unroll
        for (int j = 0; j < 4; ++j) acc[ni][j] = 0.0f;

    for (int kt = 0; kt < NTILES; ++kt) {
        if (kt == NTILES - 1) cpasync_wait0(); else cpasync_wait1();
        __syncthreads();

        if (kt + 2 < NTILES) LOAD_TILE((kt + 2) % 3, kt + 2);

        const uint32_t stgu = sb + STG0_B + (uint32_t)(kt % 3) * STG_SZ;
        const uint32_t Kadr = stgu + STG_K;
        const uint32_t Vadr = stgu + STG_V;
        const float* Bcur = (const float*)(smc + (stgu - sb) + STG_BI);

        // S = Q @ K^T via ldmatrix: 4 kcb x (1 A-ldsm + 1 B-ldsm-pair)
        float s[4][4];
#pragma unroll
        for (int ni = 0; ni < 4; ++ni)
#pragma unroll
            for (int j = 0; j < 4; ++j) s[ni][j] = 0.0f;
#pragma unroll
        for (int kcb = 0; kcb < 4; ++kcb) {
            uint32_t a[4];
            ldsm_x4(a[0], a[1], a[2], a[3], sb + QS_B + aoffQ + kcb * 32);
            uint32_t bf[4][2];
#pragma unroll
            for (int a2 = 0; a2 < 2; ++a2) {
                uint32_t r0, r1, r2, r3;
                ldsm_x4(r0, r1, r2, r3,
                        Kadr + boffK + a2 * (16 * QPITCH) + kcb * 32);
                bf[2 * a2][0] = r0;     bf[2 * a2][1] = r1;
                bf[2 * a2 + 1][0] = r2; bf[2 * a2 + 1][1] = r3;
            }
#pragma unroll
            for (int ni = 0; ni < 4; ++ni)
                mma_f16(s[ni], a, bf[ni]);
        }

        // mask + bias (staged smem) + exp; pack P to fp16 (A-frag ready)
        uint32_t plo[4], phi[4];
#pragma unroll
        for (int ni = 0; ni < 4; ++ni) {
            const int bco = ni * 8 + tg * 2;
            float2 b0 = *(const float2*)(Bcur + (qb + g) * BPADF + bco);
            float2 b1 = *(const float2*)(Bcur + (qb + g + 8) * BPADF + bco);
            const float p00 = fexp((s[ni][0] == 0.0f ? NEGV : s[ni][0]) + b0.x);
            const float p01 = fexp((s[ni][1] == 0.0f ? NEGV : s[ni][1]) + b0.y);
            const float p10 = fexp((s[ni][2] == 0.0f ? NEGV : s[ni][2]) + b1.x);
            const float p11 = fexp((s[ni][3] == 0.0f ? NEGV : s[ni][3]) + b1.y);
            l0 += p00 + p01;
            l1 += p10 + p11;
            __half2 hlo = __float22half2_rn(make_float2(p00, p01));
            __half2 hhi = __float22half2_rn(make_float2(p10, p11));
            plo[ni] = *(const uint32_t*)&hlo;
            phi[ni] = *(const uint32_t*)&hhi;
        }

        // acc += P @ V via ldmatrix B-frags (pitch 80, conflict-free)
#pragma unroll
        for (int j = 0; j < 2; ++j) {
            uint32_t a[4];
            a[0] = plo[2 * j];
            a[1] = phi[2 * j];
            a[2] = plo[2 * j + 1];
            a[3] = phi[2 * j + 1];
            uint32_t bf[8][2];
#pragma unroll
            for (int a2 = 0; a2 < 4; ++a2) {
                uint32_t r0, r1, r2, r3;
                ldsm_x4(r0, r1, r2, r3,
                        Vadr + boffV + a2 * (16 * VPITCH) + j * 32);
                bf[2 * a2][0] = r0;     bf[2 * a2][1] = r1;
                bf[2 * a2 + 1][0] = r2; bf[2 * a2 + 1][1] = r3;
            }
#pragma unroll
            for (int ni = 0; ni < 8; ++ni)
                mma_f16(acc[ni], a, bf[ni]);
        }
    }

    l0 += __shfl_xor_sync(0xffffffffu, l0, 1);
    l0 += __shfl_xor_sync(0xffffffffu, l0, 2);
    l1 += __shfl_xor_sync(0xffffffffu, l1, 1);
    l1 += __shfl_xor_sync(0xffffffffu, l1, 2);

    const float inv0 = 1.0f / l0;
    const float inv1 = 1.0f / l1;
#pragma unroll
    for (int ni = 0; ni < 8; ++ni) {
        const int col = h * DK + ni * 8 + tg * 2;
        __half* o0 = O + (size_t)(b * S_LEN + qrow0) * HID + col;
        __half* o1 = O + (size_t)(b * S_LEN + qrow0 + 8) * HID + col;
        *(__half2*)o0 = __float22half2_rn(
            make_float2(acc[ni][0] * inv0, acc[ni][1] * inv0));
        *(__half2*)o1 = __float22half2_rn(
            make_float2(acc[ni][2] * inv1, acc[ni][3] * inv1));
    }
}

// ---------------------------------------------------------------------------
extern "C" void kernel_launch(void* const* d_in, const int* in_sizes, int n_in,
                              void* d_out, int out_size)
{
    const float* batch = (const float*)d_in[0];
    const float* bias  = (const float*)d_in[1];
    const float* Wq = (const float*)d_in[2];
    const float* bq = (const float*)d_in[3];
    const float* Wk = (const float*)d_in[4];
    const float* bk = (const float*)d_in[5];
    const float* Wv = (const float*)d_in[6];
    const float* bv = (const float*)d_in[7];
    const float* Wo = (const float*)d_in[8];
    const float* bo = (const float*)d_in[9];
    float* out = (float*)d_out;

    __half *qptr, *kptr, *vtptr, *aptr, *xptr, *wqp, *wkp, *wvp, *wop;
    cudaGetSymbolAddress((void**)&qptr, g_q16);
    cudaGetSymbolAddress((void**)&kptr, g_k16);
    cudaGetSymbolAddress((void**)&vtptr, g_vt16);
    cudaGetSymbolAddress((void**)&aptr, g_att16);
    cudaGetSymbolAddress((void**)&xptr, g_x16);
    cudaGetSymbolAddress((void**)&wqp, g_wq16);
    cudaGetSymbolAddress((void**)&wkp, g_wk16);
    cudaGetSymbolAddress((void**)&wvp, g_wv16);
    cudaGetSymbolAddress((void**)&wop, g_wo16);

    static int attr_set = 0;
    if (!attr_set) {
        cudaFuncSetAttribute(gemm_qkv,
                             cudaFuncAttributeMaxDynamicSharedMemorySize,
                             GEMM_SMEM_BYTES);
        cudaFuncSetAttribute(gemm_o,
                             cudaFuncAttributeMaxDynamicSharedMemorySize,
                             GEMM_SMEM_BYTES);
        cudaFuncSetAttribute(attn_mma,
                             cudaFuncAttributeMaxDynamicSharedMemorySize,
                             ATTN_SMEM_BYTES);
        attr_set = 1;
    }

    const int totalG = G8X + 4 * G8W;
    round_all16<<<totalG / 256, 256>>>(
        (const float4*)batch, (const float4*)Wq, (const float4*)Wk,
        (const float4*)Wv, (const float4*)Wo,
        xptr, wqp, wkp, wvp, wop);

    dim3 qkvgrid(24, 32);
    gemm_qkv<<<qkvgrid, 256, GEMM_SMEM_BYTES>>>(xptr, wqp, wkp, wvp,
                                                bq, bk, bv, qptr, kptr, vtptr);

    dim3 agrid(S_LEN / 128, NH, BATCH);
    attn_mma<<<agrid, 256, ATTN_SMEM_BYTES>>>(qptr, kptr, vtptr, bias, aptr);

    dim3 ogrid(HID / 128, M_TOT / 128);
    gemm_o<<<ogrid, 256, GEMM_SMEM_BYTES>>>(aptr, wop, bo, out);
}